// round 1
// baseline (speedup 1.0000x reference)
#include <cuda_runtime.h>
#include <math.h>

#define N_NODES 10000
#define N_EDGES 120000
#define E_TOT   130000      // edges + self loops
#define F_IN    66
#define HEADS   10
#define FHEAD   66
#define D1      660         // HEADS*FHEAD
#define D2      1320        // GCN out
#define D3      1000
#define D4      64

// ---------------- scratch (static device globals; no allocation allowed) ----
__device__ __align__(16) float g_xt [N_NODES * D1];   // x @ W_gat
__device__             float g_as [N_NODES * HEADS];
__device__             float g_ad [N_NODES * HEADS];
__device__             float g_ssum[N_NODES * HEADS]; // softmax denominators
__device__             float g_deg [N_NODES];
__device__             float g_dinv[N_NODES];
__device__ __align__(16) float g_h1 [N_NODES * D1];   // GAT out (accum -> activated)
__device__ __align__(16) float g_agg[N_NODES * D1];   // GCN pre-GEMM aggregate
__device__ __align__(16) float g_h2 [N_NODES * D2];
__device__ __align__(16) float g_h3 [N_NODES * D3];
__device__ __align__(16) float g_h4 [N_NODES * D4];

// ---------------- helpers ---------------------------------------------------
__device__ __forceinline__ void edge_sd(const int* ei, int e, int& s, int& d) {
    if (e < N_EDGES) { s = ei[e]; d = ei[N_EDGES + e]; }
    else             { s = d = e - N_EDGES; }          // self loop
}

__device__ __forceinline__ float leaky(float v, float sl) {
    return v >= 0.f ? v : sl * v;
}

// ---------------- zero scratch ----------------------------------------------
__global__ void zero_kernel() {
    int stride = gridDim.x * blockDim.x;
    int t0 = blockIdx.x * blockDim.x + threadIdx.x;
    for (int i = t0; i < N_NODES * D1; i += stride) { g_h1[i] = 0.f; g_agg[i] = 0.f; }
    for (int i = t0; i < N_NODES * HEADS; i += stride) g_ssum[i] = 0.f;
    for (int i = t0; i < N_NODES; i += stride) g_deg[i] = 0.f;
}

// ---------------- generic tiled SGEMM: C = act(A[M,K] @ B[K,N] + bias) -------
template<bool BIAS, bool ACT>
__global__ void sgemm_kernel(const float* __restrict__ A, const float* __restrict__ B,
                             const float* __restrict__ bias, float* __restrict__ C,
                             int M, int Nn, int K) {
    const int BM = 64, BN = 64, BK = 16;
    __shared__ float As[BK][BM + 1];
    __shared__ float Bs[BK][BN];
    int tid = threadIdx.x;
    int tx = tid & 15, ty = tid >> 4;
    int m0 = blockIdx.y * BM, n0 = blockIdx.x * BN;
    float acc[4][4] = {};
    int ak = tid & 15, ar = tid >> 4;   // A-load: k-in-tile, row base
    int bc = tid & 63, bk = tid >> 6;   // B-load: col, k base

    for (int kt = 0; kt < K; kt += BK) {
        #pragma unroll
        for (int j = 0; j < 4; j++) {
            int r = ar + 16 * j;
            int gr = m0 + r, gk = kt + ak;
            As[ak][r] = (gr < M && gk < K) ? A[(long)gr * K + gk] : 0.f;
        }
        #pragma unroll
        for (int j = 0; j < 4; j++) {
            int kk = bk + 4 * j;
            int gk = kt + kk, gc = n0 + bc;
            Bs[kk][bc] = (gk < K && gc < Nn) ? B[(long)gk * Nn + gc] : 0.f;
        }
        __syncthreads();
        #pragma unroll
        for (int kk = 0; kk < BK; kk++) {
            float a[4], b[4];
            #pragma unroll
            for (int i = 0; i < 4; i++) a[i] = As[kk][ty * 4 + i];
            #pragma unroll
            for (int j = 0; j < 4; j++) b[j] = Bs[kk][tx * 4 + j];
            #pragma unroll
            for (int i = 0; i < 4; i++)
                #pragma unroll
                for (int j = 0; j < 4; j++)
                    acc[i][j] += a[i] * b[j];
        }
        __syncthreads();
    }
    #pragma unroll
    for (int i = 0; i < 4; i++) {
        int gr = m0 + ty * 4 + i;
        if (gr >= M) continue;
        #pragma unroll
        for (int j = 0; j < 4; j++) {
            int gc = n0 + tx * 4 + j;
            if (gc >= Nn) continue;
            float v = acc[i][j];
            if (BIAS) v += bias[gc];
            if (ACT)  v = leaky(v, 0.01f);
            C[(long)gr * Nn + gc] = v;
        }
    }
}

// ---------------- attention coefficients a_s, a_d ---------------------------
__global__ void attn_kernel(const float* __restrict__ att_src,
                            const float* __restrict__ att_dst) {
    int idx = blockIdx.x * blockDim.x + threadIdx.x;
    if (idx >= N_NODES * HEADS) return;
    int n = idx / HEADS, h = idx % HEADS;
    const float* xr = g_xt + n * D1 + h * FHEAD;
    const float* as = att_src + h * FHEAD;
    const float* ad = att_dst + h * FHEAD;
    float s = 0.f, d = 0.f;
    #pragma unroll
    for (int f = 0; f < FHEAD; f++) { float v = xr[f]; s += v * as[f]; d += v * ad[f]; }
    g_as[idx] = s; g_ad[idx] = d;
}

// ---------------- edge pass 1: softmax denominators + degree -----------------
// max-subtraction skipped: |e| is small (0.05-scaled weights), exp(e) is safe,
// and alpha = exp(e)/sum exp(e) is shift-invariant => identical result.
__global__ void edge_pass1_kernel(const int* __restrict__ ei) {
    int e = blockIdx.x * blockDim.x + threadIdx.x;
    if (e >= E_TOT) return;
    int src, dst; edge_sd(ei, e, src, dst);
    #pragma unroll
    for (int h = 0; h < HEADS; h++) {
        float v = g_as[src * HEADS + h] + g_ad[dst * HEADS + h];
        atomicAdd(&g_ssum[dst * HEADS + h], expf(leaky(v, 0.2f)));
    }
    atomicAdd(&g_deg[dst], 1.0f);
}

__global__ void dinv_kernel() {
    int i = blockIdx.x * blockDim.x + threadIdx.x;
    if (i < N_NODES) g_dinv[i] = rsqrtf(fmaxf(g_deg[i], 1.f));
}

// ---------------- edge pass 2: GAT message scatter (warp per edge) ----------
__global__ void gat_scatter_kernel(const int* __restrict__ ei) {
    int gw = (blockIdx.x * blockDim.x + threadIdx.x) >> 5;
    int lane = threadIdx.x & 31;
    int wl = threadIdx.x >> 5;
    __shared__ float salpha[8][HEADS];
    if (gw >= E_TOT) return;
    int src, dst; edge_sd(ei, gw, src, dst);
    if (lane < HEADS) {
        float e = g_as[src * HEADS + lane] + g_ad[dst * HEADS + lane];
        float w = expf(leaky(e, 0.2f));
        salpha[wl][lane] = w / fmaxf(g_ssum[dst * HEADS + lane], 1e-16f);
    }
    __syncwarp();
    const float4* xs = (const float4*)g_xt + src * (D1 / 4);
    float4*       od = (float4*)g_h1       + dst * (D1 / 4);
    for (int i = lane; i < D1 / 4; i += 32) {
        float4 v = xs[i];
        int f = 4 * i;
        v.x *= salpha[wl][ f      / FHEAD];
        v.y *= salpha[wl][(f + 1) / FHEAD];
        v.z *= salpha[wl][(f + 2) / FHEAD];
        v.w *= salpha[wl][(f + 3) / FHEAD];
        atomicAdd(&od[i], v);        // RED.128, sm_90+
    }
}

// ---------------- GAT finalize: bias + leaky(0.01), in place ----------------
__global__ void gat_finalize_kernel(const float* __restrict__ b_gat) {
    int idx = blockIdx.x * blockDim.x + threadIdx.x;
    if (idx >= N_NODES * D1) return;
    g_h1[idx] = leaky(g_h1[idx] + b_gat[idx % D1], 0.01f);
}

// ---------------- GCN aggregate in 660-dim (BEFORE the GEMM; linearity) -----
__global__ void gcn_agg_kernel(const int* __restrict__ ei) {
    int gw = (blockIdx.x * blockDim.x + threadIdx.x) >> 5;
    int lane = threadIdx.x & 31;
    if (gw >= E_TOT) return;
    int src, dst; edge_sd(ei, gw, src, dst);
    float norm = g_dinv[src] * g_dinv[dst];
    const float4* hs = (const float4*)g_h1 + src * (D1 / 4);
    float4*       ag = (float4*)g_agg      + dst * (D1 / 4);
    for (int i = lane; i < D1 / 4; i += 32) {
        float4 v = hs[i];
        v.x *= norm; v.y *= norm; v.z *= norm; v.w *= norm;
        atomicAdd(&ag[i], v);
    }
}

// ---------------- tail: fc1(64->32) fc2(32->16) out(16->1), warp per node ---
__global__ void tail_kernel(const float* __restrict__ W1, const float* __restrict__ b1,
                            const float* __restrict__ W2, const float* __restrict__ b2,
                            const float* __restrict__ W3, const float* __restrict__ b3,
                            float* __restrict__ out) {
    int gw = (blockIdx.x * blockDim.x + threadIdx.x) >> 5;
    int lane = threadIdx.x & 31;
    if (gw >= N_NODES) return;
    float v0 = g_h4[gw * 64 + lane];
    float v1 = g_h4[gw * 64 + 32 + lane];
    float s = b1[lane];
    #pragma unroll
    for (int k = 0; k < 32; k++) s += __shfl_sync(0xffffffffu, v0, k) * W1[k * 32 + lane];
    #pragma unroll
    for (int k = 0; k < 32; k++) s += __shfl_sync(0xffffffffu, v1, k) * W1[(k + 32) * 32 + lane];
    float u = leaky(s, 0.01f);
    int j = lane & 15;
    float s2 = b2[j];
    #pragma unroll
    for (int k = 0; k < 32; k++) s2 += __shfl_sync(0xffffffffu, u, k) * W2[k * 16 + j];
    float t = leaky(s2, 0.01f);
    float o = (lane < 16) ? t * W3[lane] : 0.f;
    #pragma unroll
    for (int off = 8; off > 0; off >>= 1) o += __shfl_down_sync(0xffffffffu, o, off);
    if (lane == 0) out[gw] = o + b3[0];
}

// ---------------- launch ------------------------------------------------------
extern "C" void kernel_launch(void* const* d_in, const int* in_sizes, int n_in,
                              void* d_out, int out_size) {
    const float* x     = (const float*)d_in[0];
    const int*   ei    = (const int*)  d_in[1];
    const float* W_gat = (const float*)d_in[2];
    const float* att_s = (const float*)d_in[3];
    const float* att_d = (const float*)d_in[4];
    const float* b_gat = (const float*)d_in[5];
    const float* W_gcn = (const float*)d_in[6];
    const float* b_gcn = (const float*)d_in[7];
    const float* W_g1  = (const float*)d_in[8];
    const float* b_g1  = (const float*)d_in[9];
    const float* W_g2  = (const float*)d_in[10];
    const float* b_g2  = (const float*)d_in[11];
    const float* W_fc1 = (const float*)d_in[12];
    const float* b_fc1 = (const float*)d_in[13];
    const float* W_fc2 = (const float*)d_in[14];
    const float* b_fc2 = (const float*)d_in[15];
    const float* W_out = (const float*)d_in[16];
    const float* b_out = (const float*)d_in[17];
    float* out = (float*)d_out;

    float *p_xt, *p_h1, *p_agg, *p_h2, *p_h3, *p_h4;
    cudaGetSymbolAddress((void**)&p_xt,  g_xt);
    cudaGetSymbolAddress((void**)&p_h1,  g_h1);
    cudaGetSymbolAddress((void**)&p_agg, g_agg);
    cudaGetSymbolAddress((void**)&p_h2,  g_h2);
    cudaGetSymbolAddress((void**)&p_h3,  g_h3);
    cudaGetSymbolAddress((void**)&p_h4,  g_h4);
    (void)p_h1; (void)in_sizes; (void)n_in; (void)out_size;

    zero_kernel<<<4096, 256>>>();

    // GAT linear: xt = x @ W_gat
    sgemm_kernel<false, false><<<dim3((D1 + 63) / 64, (N_NODES + 63) / 64), 256>>>(
        x, W_gat, nullptr, p_xt, N_NODES, D1, F_IN);

    attn_kernel<<<(N_NODES * HEADS + 255) / 256, 256>>>(att_s, att_d);
    edge_pass1_kernel<<<(E_TOT + 255) / 256, 256>>>(ei);
    dinv_kernel<<<(N_NODES + 255) / 256, 256>>>();
    gat_scatter_kernel<<<(E_TOT * 32 + 255) / 256, 256>>>(ei);
    gat_finalize_kernel<<<(N_NODES * D1 + 255) / 256, 256>>>(b_gat);
    gcn_agg_kernel<<<(E_TOT * 32 + 255) / 256, 256>>>(ei);

    // GCN linear (post-aggregation): h2 = leaky(agg @ W_gcn + b)
    sgemm_kernel<true, true><<<dim3((D2 + 63) / 64, (N_NODES + 63) / 64), 256>>>(
        p_agg, W_gcn, b_gcn, p_h2, N_NODES, D2, D1);
    // h3 = leaky(h2 @ W_g1 + b)
    sgemm_kernel<true, true><<<dim3((D3 + 63) / 64, (N_NODES + 63) / 64), 256>>>(
        p_h2, W_g1, b_g1, p_h3, N_NODES, D3, D2);
    // h4 = leaky(h3 @ W_g2 + b)
    sgemm_kernel<true, true><<<dim3((D4 + 63) / 64, (N_NODES + 63) / 64), 256>>>(
        p_h3, W_g2, b_g2, p_h4, N_NODES, D4, D3);

    tail_kernel<<<(N_NODES * 32 + 255) / 256, 256>>>(
        W_fc1, b_fc1, W_fc2, b_fc2, W_out, b_out, out);
}

// round 3
// speedup vs baseline: 1.8067x; 1.8067x over previous
#include <cuda_runtime.h>
#include <cuda_bf16.h>
#include <math.h>
#include <stdint.h>

#define N_NODES 10000
#define N_EDGES 120000
#define E_TOT   130000
#define F_IN    66
#define HEADS   10
#define FHEAD   66
#define D1      660
#define D2      1320
#define D3      1000
#define D4      64
#define M_PAD   10112        // 79 * 128

// K paddings (multiples of 64) and N paddings (multiples of 128)
#define KP_X    128
#define KP_AGG  704
#define KP_H2   1344
#define KP_H3   1024
#define NP_GAT  768
#define NP_GCN  1408
#define NP_G1   1024
#define NP_G2   128

// ---------------- fp32 scratch ----------------------------------------------
__device__ __align__(16) float g_xt [N_NODES * D1];
__device__             float g_as [N_NODES * HEADS];
__device__             float g_ad [N_NODES * HEADS];
__device__             float g_ssum[N_NODES * HEADS];
__device__             float g_deg [N_NODES];
__device__             float g_dinv[N_NODES];
__device__ __align__(16) float g_h1 [N_NODES * D1];
__device__ __align__(16) float g_agg[N_NODES * D1];
__device__ __align__(16) float g_h2 [N_NODES * D2];
__device__ __align__(16) float g_h3 [N_NODES * D3];
__device__ __align__(16) float g_h4 [N_NODES * D4];

// ---------------- bf16 hi/lo split buffers ----------------------------------
__device__ __align__(16) __nv_bfloat16 g_axh [M_PAD * KP_X];
__device__ __align__(16) __nv_bfloat16 g_axl [M_PAD * KP_X];
__device__ __align__(16) __nv_bfloat16 g_aah [M_PAD * KP_AGG];
__device__ __align__(16) __nv_bfloat16 g_aal [M_PAD * KP_AGG];
__device__ __align__(16) __nv_bfloat16 g_a2h [M_PAD * KP_H2];
__device__ __align__(16) __nv_bfloat16 g_a2l [M_PAD * KP_H2];
__device__ __align__(16) __nv_bfloat16 g_a3h [M_PAD * KP_H3];
__device__ __align__(16) __nv_bfloat16 g_a3l [M_PAD * KP_H3];
__device__ __align__(16) __nv_bfloat16 g_bgath[NP_GAT * KP_X];
__device__ __align__(16) __nv_bfloat16 g_bgatl[NP_GAT * KP_X];
__device__ __align__(16) __nv_bfloat16 g_bgcnh[NP_GCN * KP_AGG];
__device__ __align__(16) __nv_bfloat16 g_bgcnl[NP_GCN * KP_AGG];
__device__ __align__(16) __nv_bfloat16 g_bg1h [NP_G1 * KP_H2];
__device__ __align__(16) __nv_bfloat16 g_bg1l [NP_G1 * KP_H2];
__device__ __align__(16) __nv_bfloat16 g_bg2h [NP_G2 * KP_H3];
__device__ __align__(16) __nv_bfloat16 g_bg2l [NP_G2 * KP_H3];

// ---------------- baseline-PTX helpers (sm_80+, compile under compute_103) --
__device__ __forceinline__ uint32_t smem_u32(const void* p) {
    uint32_t a;
    asm("{ .reg .u64 t; cvta.to.shared.u64 t, %1; cvt.u32.u64 %0, t; }" : "=r"(a) : "l"(p));
    return a;
}
__device__ __forceinline__ void cp16(uint32_t dst, const void* src) {
    asm volatile("cp.async.cg.shared.global [%0], [%1], 16;" :: "r"(dst), "l"(src));
}
__device__ __forceinline__ void cp_commit() { asm volatile("cp.async.commit_group;"); }
template<int N> __device__ __forceinline__ void cp_wait() {
    asm volatile("cp.async.wait_group %0;" :: "n"(N));
}
__device__ __forceinline__ void ldsm4(uint32_t* r, uint32_t addr) {
    asm volatile("ldmatrix.sync.aligned.m8n8.x4.shared.b16 {%0,%1,%2,%3}, [%4];"
        : "=r"(r[0]), "=r"(r[1]), "=r"(r[2]), "=r"(r[3]) : "r"(addr));
}
__device__ __forceinline__ void mma_bf16(float* d, const uint32_t* a, const uint32_t* b) {
    asm volatile("mma.sync.aligned.m16n8k16.row.col.f32.bf16.bf16.f32 "
        "{%0,%1,%2,%3}, {%4,%5,%6,%7}, {%8,%9}, {%0,%1,%2,%3};"
        : "+f"(d[0]), "+f"(d[1]), "+f"(d[2]), "+f"(d[3])
        : "r"(a[0]), "r"(a[1]), "r"(a[2]), "r"(a[3]), "r"(b[0]), "r"(b[1]));
}

// ---------------- misc helpers ----------------------------------------------
__device__ __forceinline__ void edge_sd(const int* ei, int e, int& s, int& d) {
    if (e < N_EDGES) { s = ei[e]; d = ei[N_EDGES + e]; }
    else             { s = d = e - N_EDGES; }
}
__device__ __forceinline__ float leaky(float v, float sl) { return v >= 0.f ? v : sl * v; }

// ---------------- zero scratch ----------------------------------------------
__global__ void zero_kernel() {
    int stride = gridDim.x * blockDim.x;
    int t0 = blockIdx.x * blockDim.x + threadIdx.x;
    for (int i = t0; i < N_NODES * D1; i += stride) { g_h1[i] = 0.f; g_agg[i] = 0.f; }
    for (int i = t0; i < N_NODES * HEADS; i += stride) g_ssum[i] = 0.f;
    for (int i = t0; i < N_NODES; i += stride) g_deg[i] = 0.f;
}

// ---------------- bf16 hi/lo splits ------------------------------------------
__global__ void cvtA_kernel(const float* __restrict__ in,
                            __nv_bfloat16* __restrict__ hi, __nv_bfloat16* __restrict__ lo,
                            int K, int Kp, int total) {
    int idx = blockIdx.x * blockDim.x + threadIdx.x;
    if (idx >= total) return;
    int r = idx / Kp, c = idx - r * Kp;
    float v = (r < N_NODES && c < K) ? in[(long)r * K + c] : 0.f;
    __nv_bfloat16 h = __float2bfloat16(v);
    hi[idx] = h;
    lo[idx] = __float2bfloat16(v - __bfloat162float(h));
}
// B: fp32 W[K, N] -> transposed hi/lo [Np, Kp] (row n, col k = W[k*N+n])
__global__ void cvtB_kernel(const float* __restrict__ W,
                            __nv_bfloat16* __restrict__ hi, __nv_bfloat16* __restrict__ lo,
                            int K, int Nn, int Kp, int total) {
    int idx = blockIdx.x * blockDim.x + threadIdx.x;
    if (idx >= total) return;
    int n = idx / Kp, k = idx - n * Kp;
    float v = (k < K && n < Nn) ? W[(long)k * Nn + n] : 0.f;
    __nv_bfloat16 h = __float2bfloat16(v);
    hi[idx] = h;
    lo[idx] = __float2bfloat16(v - __bfloat162float(h));
}

// ---------------- HMMA GEMM: C[m,n] = act(sum_k A[m,k]*Bt[n,k] + bias) -------
// 128x128 tile, BK=32, 3-stage cp.async, bf16x3 split, 80B smem row stride.
#define TSTRIDE  80
#define MAT_SZ   10240       // 128 rows * 80B
#define A_LO_OFF 10240
#define B_HI_OFF 20480
#define B_LO_OFF 30720
#define STAGE_SZ 40960
#define GEMM_SMEM (3 * STAGE_SZ)

__device__ __forceinline__ void fill_stage(uint32_t st,
        const __nv_bfloat16* __restrict__ Ah, const __nv_bfloat16* __restrict__ Al,
        const __nv_bfloat16* __restrict__ Bh, const __nv_bfloat16* __restrict__ Bl,
        int m0, int n0, int Kp, int k0, int tid) {
    #pragma unroll
    for (int i = 0; i < 2; i++) {
        int lin = tid + i * 256;
        int r = lin >> 2, cc = lin & 3;
        uint32_t d = st + r * TSTRIDE + cc * 16;
        long aoff = (long)(m0 + r) * Kp + k0;
        long boff = (long)(n0 + r) * Kp + k0;
        cp16(d,            (const char*)(Ah + aoff) + cc * 16);
        cp16(d + A_LO_OFF, (const char*)(Al + aoff) + cc * 16);
        cp16(d + B_HI_OFF, (const char*)(Bh + boff) + cc * 16);
        cp16(d + B_LO_OFF, (const char*)(Bl + boff) + cc * 16);
    }
    cp_commit();
}

template<bool BIAS, bool ACT>
__global__ __launch_bounds__(256, 1)
void mma_gemm(const __nv_bfloat16* __restrict__ Ah, const __nv_bfloat16* __restrict__ Al,
              const __nv_bfloat16* __restrict__ Bh, const __nv_bfloat16* __restrict__ Bl,
              const float* __restrict__ bias, float* __restrict__ C,
              int Kp, int chunks, int Nreal, int ldC) {
    extern __shared__ char smem[];
    const uint32_t tile0 = smem_u32(smem);
    const int tid = threadIdx.x, wid = tid >> 5, lane = tid & 31;
    const int m0 = blockIdx.y * 128, n0 = blockIdx.x * 128;
    const int mwoff = (wid >> 1) * 32, nwoff = (wid & 1) * 64;

    // per-thread ldmatrix offsets (lane supplies row for matrix lane>>3)
    const int mat = lane >> 3, mrow = lane & 7;
    uint32_t a_off[2], b_off[4];
    #pragma unroll
    for (int ti = 0; ti < 2; ti++)
        a_off[ti] = (uint32_t)((mwoff + ti * 16 + ((mat & 1) << 3) + mrow) * TSTRIDE
                               + (mat >> 1) * 16);
    #pragma unroll
    for (int nt = 0; nt < 4; nt++)
        b_off[nt] = (uint32_t)((nwoff + nt * 16 + ((mat >> 1) << 3) + mrow) * TSTRIDE
                               + (mat & 1) * 16);

    float acc[2][8][4] = {};

    // prologue
    fill_stage(tile0, Ah, Al, Bh, Bl, m0, n0, Kp, 0, tid);
    if (chunks > 1) fill_stage(tile0 + STAGE_SZ, Ah, Al, Bh, Bl, m0, n0, Kp, 32, tid);

    for (int c = 0; c < chunks; c++) {
        if (c + 1 < chunks) cp_wait<1>(); else cp_wait<0>();
        __syncthreads();
        if (c + 2 < chunks)
            fill_stage(tile0 + ((c + 2) % 3) * STAGE_SZ, Ah, Al, Bh, Bl,
                       m0, n0, Kp, (c + 2) * 32, tid);
        uint32_t sb = tile0 + (c % 3) * STAGE_SZ;
        #pragma unroll
        for (int kh = 0; kh < 2; kh++) {
            uint32_t ah[2][4], al[2][4], bh[4][4], bl[4][4];
            #pragma unroll
            for (int ti = 0; ti < 2; ti++) {
                ldsm4(ah[ti], sb + a_off[ti] + kh * 32);
                ldsm4(al[ti], sb + A_LO_OFF + a_off[ti] + kh * 32);
            }
            #pragma unroll
            for (int nt = 0; nt < 4; nt++) {
                ldsm4(bh[nt], sb + B_HI_OFF + b_off[nt] + kh * 32);
                ldsm4(bl[nt], sb + B_LO_OFF + b_off[nt] + kh * 32);
            }
            #pragma unroll
            for (int ti = 0; ti < 2; ti++)
                #pragma unroll
                for (int nt = 0; nt < 8; nt++) {
                    const uint32_t* ph = &bh[nt >> 1][(nt & 1) * 2];
                    const uint32_t* pl = &bl[nt >> 1][(nt & 1) * 2];
                    mma_bf16(acc[ti][nt], ah[ti], ph);
                    mma_bf16(acc[ti][nt], ah[ti], pl);
                    mma_bf16(acc[ti][nt], al[ti], ph);
                }
        }
    }

    // epilogue: c-frag: rows (lane>>2)+{0,8}, cols (lane&3)*2+{0,1}
    const int lr = lane >> 2, lc = (lane & 3) * 2;
    #pragma unroll
    for (int ti = 0; ti < 2; ti++)
        #pragma unroll
        for (int rp = 0; rp < 2; rp++) {
            int gr = m0 + mwoff + ti * 16 + rp * 8 + lr;
            if (gr >= N_NODES) continue;
            float* crow = C + (long)gr * ldC;
            #pragma unroll
            for (int nt = 0; nt < 8; nt++) {
                int gc = n0 + nwoff + nt * 8 + lc;
                float v0 = acc[ti][nt][rp * 2 + 0];
                float v1 = acc[ti][nt][rp * 2 + 1];
                if (gc < Nreal) {
                    if (BIAS) v0 += bias[gc];
                    if (ACT)  v0 = leaky(v0, 0.01f);
                    crow[gc] = v0;
                }
                if (gc + 1 < Nreal) {
                    if (BIAS) v1 += bias[gc + 1];
                    if (ACT)  v1 = leaky(v1, 0.01f);
                    crow[gc + 1] = v1;
                }
            }
        }
}

// ---------------- attention coefficients ------------------------------------
__global__ void attn_kernel(const float* __restrict__ att_src,
                            const float* __restrict__ att_dst) {
    int idx = blockIdx.x * blockDim.x + threadIdx.x;
    if (idx >= N_NODES * HEADS) return;
    int n = idx / HEADS, h = idx % HEADS;
    const float* xr = g_xt + n * D1 + h * FHEAD;
    const float* as = att_src + h * FHEAD;
    const float* ad = att_dst + h * FHEAD;
    float s = 0.f, d = 0.f;
    #pragma unroll
    for (int f = 0; f < FHEAD; f++) { float v = xr[f]; s += v * as[f]; d += v * ad[f]; }
    g_as[idx] = s; g_ad[idx] = d;
}

// ---------------- edge pass 1 -------------------------------------------------
__global__ void edge_pass1_kernel(const int* __restrict__ ei) {
    int e = blockIdx.x * blockDim.x + threadIdx.x;
    if (e >= E_TOT) return;
    int src, dst; edge_sd(ei, e, src, dst);
    #pragma unroll
    for (int h = 0; h < HEADS; h++) {
        float v = g_as[src * HEADS + h] + g_ad[dst * HEADS + h];
        atomicAdd(&g_ssum[dst * HEADS + h], expf(leaky(v, 0.2f)));
    }
    atomicAdd(&g_deg[dst], 1.0f);
}

__global__ void dinv_kernel() {
    int i = blockIdx.x * blockDim.x + threadIdx.x;
    if (i < N_NODES) g_dinv[i] = rsqrtf(fmaxf(g_deg[i], 1.f));
}

// ---------------- GAT scatter (warp per edge) --------------------------------
__global__ void gat_scatter_kernel(const int* __restrict__ ei) {
    int gw = (blockIdx.x * blockDim.x + threadIdx.x) >> 5;
    int lane = threadIdx.x & 31;
    int wl = threadIdx.x >> 5;
    __shared__ float salpha[8][HEADS];
    if (gw >= E_TOT) return;
    int src, dst; edge_sd(ei, gw, src, dst);
    if (lane < HEADS) {
        float e = g_as[src * HEADS + lane] + g_ad[dst * HEADS + lane];
        float w = expf(leaky(e, 0.2f));
        salpha[wl][lane] = w / fmaxf(g_ssum[dst * HEADS + lane], 1e-16f);
    }
    __syncwarp();
    const float4* xs = (const float4*)g_xt + src * (D1 / 4);
    float4*       od = (float4*)g_h1       + dst * (D1 / 4);
    for (int i = lane; i < D1 / 4; i += 32) {
        float4 v = xs[i];
        int f = 4 * i;
        v.x *= salpha[wl][ f      / FHEAD];
        v.y *= salpha[wl][(f + 1) / FHEAD];
        v.z *= salpha[wl][(f + 2) / FHEAD];
        v.w *= salpha[wl][(f + 3) / FHEAD];
        atomicAdd(&od[i], v);
    }
}

__global__ void gat_finalize_kernel(const float* __restrict__ b_gat) {
    int idx = blockIdx.x * blockDim.x + threadIdx.x;
    if (idx >= N_NODES * D1) return;
    g_h1[idx] = leaky(g_h1[idx] + b_gat[idx % D1], 0.01f);
}

__global__ void gcn_agg_kernel(const int* __restrict__ ei) {
    int gw = (blockIdx.x * blockDim.x + threadIdx.x) >> 5;
    int lane = threadIdx.x & 31;
    if (gw >= E_TOT) return;
    int src, dst; edge_sd(ei, gw, src, dst);
    float norm = g_dinv[src] * g_dinv[dst];
    const float4* hs = (const float4*)g_h1 + src * (D1 / 4);
    float4*       ag = (float4*)g_agg      + dst * (D1 / 4);
    for (int i = lane; i < D1 / 4; i += 32) {
        float4 v = hs[i];
        v.x *= norm; v.y *= norm; v.z *= norm; v.w *= norm;
        atomicAdd(&ag[i], v);
    }
}

// ---------------- tail --------------------------------------------------------
__global__ void tail_kernel(const float* __restrict__ W1, const float* __restrict__ b1,
                            const float* __restrict__ W2, const float* __restrict__ b2,
                            const float* __restrict__ W3, const float* __restrict__ b3,
                            float* __restrict__ out) {
    int gw = (blockIdx.x * blockDim.x + threadIdx.x) >> 5;
    int lane = threadIdx.x & 31;
    if (gw >= N_NODES) return;
    float v0 = g_h4[gw * 64 + lane];
    float v1 = g_h4[gw * 64 + 32 + lane];
    float s = b1[lane];
    #pragma unroll
    for (int k = 0; k < 32; k++) s += __shfl_sync(0xffffffffu, v0, k) * W1[k * 32 + lane];
    #pragma unroll
    for (int k = 0; k < 32; k++) s += __shfl_sync(0xffffffffu, v1, k) * W1[(k + 32) * 32 + lane];
    float u = leaky(s, 0.01f);
    int j = lane & 15;
    float s2 = b2[j];
    #pragma unroll
    for (int k = 0; k < 32; k++) s2 += __shfl_sync(0xffffffffu, u, k) * W2[k * 16 + j];
    float t = leaky(s2, 0.01f);
    float o = (lane < 16) ? t * W3[lane] : 0.f;
    #pragma unroll
    for (int off = 8; off > 0; off >>= 1) o += __shfl_down_sync(0xffffffffu, o, off);
    if (lane == 0) out[gw] = o + b3[0];
}

// ---------------- launch ------------------------------------------------------
extern "C" void kernel_launch(void* const* d_in, const int* in_sizes, int n_in,
                              void* d_out, int out_size) {
    const float* x     = (const float*)d_in[0];
    const int*   ei    = (const int*)  d_in[1];
    const float* W_gat = (const float*)d_in[2];
    const float* att_s = (const float*)d_in[3];
    const float* att_d = (const float*)d_in[4];
    const float* b_gat = (const float*)d_in[5];
    const float* W_gcn = (const float*)d_in[6];
    const float* b_gcn = (const float*)d_in[7];
    const float* W_g1  = (const float*)d_in[8];
    const float* b_g1  = (const float*)d_in[9];
    const float* W_g2  = (const float*)d_in[10];
    const float* b_g2  = (const float*)d_in[11];
    const float* W_fc1 = (const float*)d_in[12];
    const float* b_fc1 = (const float*)d_in[13];
    const float* W_fc2 = (const float*)d_in[14];
    const float* b_fc2 = (const float*)d_in[15];
    const float* W_out = (const float*)d_in[16];
    const float* b_out = (const float*)d_in[17];
    float* out = (float*)d_out;
    (void)in_sizes; (void)n_in; (void)out_size;

    cudaFuncSetAttribute(mma_gemm<false, false>, cudaFuncAttributeMaxDynamicSharedMemorySize, GEMM_SMEM);
    cudaFuncSetAttribute(mma_gemm<true, true>,   cudaFuncAttributeMaxDynamicSharedMemorySize, GEMM_SMEM);

    #define SYMADDR(p, s) float* p; cudaGetSymbolAddress((void**)&p, s)
    SYMADDR(p_xt, g_xt); SYMADDR(p_h2, g_h2); SYMADDR(p_h3, g_h3);
    SYMADDR(p_h4, g_h4); SYMADDR(p_agg, g_agg);
    #define BFADDR(p, s) __nv_bfloat16* p; cudaGetSymbolAddress((void**)&p, s)
    BFADDR(axh, g_axh); BFADDR(axl, g_axl);
    BFADDR(aah, g_aah); BFADDR(aal, g_aal);
    BFADDR(a2h, g_a2h); BFADDR(a2l, g_a2l);
    BFADDR(a3h, g_a3h); BFADDR(a3l, g_a3l);
    BFADDR(bgath, g_bgath); BFADDR(bgatl, g_bgatl);
    BFADDR(bgcnh, g_bgcnh); BFADDR(bgcnl, g_bgcnl);
    BFADDR(bg1h, g_bg1h); BFADDR(bg1l, g_bg1l);
    BFADDR(bg2h, g_bg2h); BFADDR(bg2l, g_bg2l);

    zero_kernel<<<4096, 256>>>();

    // weight splits (independent; launch early)
    cvtB_kernel<<<(NP_GAT * KP_X + 255) / 256, 256>>>(W_gat, bgath, bgatl, F_IN, D1, KP_X, NP_GAT * KP_X);
    cvtB_kernel<<<(NP_GCN * KP_AGG + 255) / 256, 256>>>(W_gcn, bgcnh, bgcnl, D1, D2, KP_AGG, NP_GCN * KP_AGG);
    cvtB_kernel<<<(NP_G1 * KP_H2 + 255) / 256, 256>>>(W_g1, bg1h, bg1l, D2, D3, KP_H2, NP_G1 * KP_H2);
    cvtB_kernel<<<(NP_G2 * KP_H3 + 255) / 256, 256>>>(W_g2, bg2h, bg2l, D3, D4, KP_H3, NP_G2 * KP_H3);

    // GAT linear: xt = x @ W_gat
    cvtA_kernel<<<(M_PAD * KP_X + 255) / 256, 256>>>(x, axh, axl, F_IN, KP_X, M_PAD * KP_X);
    mma_gemm<false, false><<<dim3(NP_GAT / 128, M_PAD / 128), 256, GEMM_SMEM>>>(
        axh, axl, bgath, bgatl, nullptr, p_xt, KP_X, KP_X / 32, D1, D1);

    attn_kernel<<<(N_NODES * HEADS + 255) / 256, 256>>>(att_s, att_d);
    edge_pass1_kernel<<<(E_TOT + 255) / 256, 256>>>(ei);
    dinv_kernel<<<(N_NODES + 255) / 256, 256>>>();
    gat_scatter_kernel<<<(E_TOT * 32 + 255) / 256, 256>>>(ei);
    gat_finalize_kernel<<<(N_NODES * D1 + 255) / 256, 256>>>(b_gat);
    gcn_agg_kernel<<<(E_TOT * 32 + 255) / 256, 256>>>(ei);

    // GCN linear
    cvtA_kernel<<<(M_PAD * KP_AGG + 255) / 256, 256>>>(p_agg, aah, aal, D1, KP_AGG, M_PAD * KP_AGG);
    mma_gemm<true, true><<<dim3(NP_GCN / 128, M_PAD / 128), 256, GEMM_SMEM>>>(
        aah, aal, bgcnh, bgcnl, b_gcn, p_h2, KP_AGG, KP_AGG / 32, D2, D2);
    // g1
    cvtA_kernel<<<(M_PAD * KP_H2 + 255) / 256, 256>>>(p_h2, a2h, a2l, D2, KP_H2, M_PAD * KP_H2);
    mma_gemm<true, true><<<dim3(NP_G1 / 128, M_PAD / 128), 256, GEMM_SMEM>>>(
        a2h, a2l, bg1h, bg1l, b_g1, p_h3, KP_H2, KP_H2 / 32, D3, D3);
    // g2
    cvtA_kernel<<<(M_PAD * KP_H3 + 255) / 256, 256>>>(p_h3, a3h, a3l, D3, KP_H3, M_PAD * KP_H3);
    mma_gemm<true, true><<<dim3(NP_G2 / 128, M_PAD / 128), 256, GEMM_SMEM>>>(
        a3h, a3l, bg2h, bg2l, b_g2, p_h4, KP_H3, KP_H3 / 32, D4, D4);

    tail_kernel<<<(N_NODES * 32 + 255) / 256, 256>>>(
        W_fc1, b_fc1, W_fc2, b_fc2, W_out, b_out, out);
}

// round 4
// speedup vs baseline: 2.1126x; 1.1693x over previous
#include <cuda_runtime.h>
#include <cuda_bf16.h>
#include <math.h>
#include <stdint.h>

#define N_NODES 10000
#define N_EDGES 120000
#define E_TOT   130000
#define F_IN    66
#define HEADS   10
#define FHEAD   66
#define D1      660
#define D2      1320
#define D3      1000
#define D4      64
#define M_PAD   10112        // 79 * 128

#define KP_X    96
#define KP_AGG  704
#define KP_H2   1344
#define KP_H3   1024
#define NP_GAT  768
#define NP_GCN  1408
#define NP_G1   1024
#define NP_G2   128

// ---------------- fp32 scratch ----------------------------------------------
__device__ __align__(16) float g_xt [N_NODES * D1];
__device__             float g_as [N_NODES * HEADS];
__device__             float g_ad [N_NODES * HEADS];
__device__             float g_dinv[N_NODES];
__device__ __align__(16) float g_h1 [N_NODES * D1];
__device__ __align__(16) float g_h4 [N_NODES * D4];
__device__ __align__(16) float g_w  [E_TOT * HEADS];   // exp(leaky(e)) per edge/head

// ---------------- CSR over destination --------------------------------------
__device__ int g_deg_i [N_NODES];
__device__ int g_fill  [N_NODES];
__device__ int g_rowptr[N_NODES + 1];
__device__ int g_csr_src[E_TOT];
__device__ int g_csr_eid[E_TOT];

// ---------------- bf16 hi/lo split buffers ----------------------------------
__device__ __align__(16) __nv_bfloat16 g_axh [M_PAD * KP_X];
__device__ __align__(16) __nv_bfloat16 g_axl [M_PAD * KP_X];
__device__ __align__(16) __nv_bfloat16 g_aah [M_PAD * KP_AGG];
__device__ __align__(16) __nv_bfloat16 g_aal [M_PAD * KP_AGG];
__device__ __align__(16) __nv_bfloat16 g_a2h [M_PAD * KP_H2];
__device__ __align__(16) __nv_bfloat16 g_a2l [M_PAD * KP_H2];
__device__ __align__(16) __nv_bfloat16 g_a3h [M_PAD * KP_H3];
__device__ __align__(16) __nv_bfloat16 g_a3l [M_PAD * KP_H3];
__device__ __align__(16) __nv_bfloat16 g_bgath[NP_GAT * KP_X];
__device__ __align__(16) __nv_bfloat16 g_bgatl[NP_GAT * KP_X];
__device__ __align__(16) __nv_bfloat16 g_bgcnh[NP_GCN * KP_AGG];
__device__ __align__(16) __nv_bfloat16 g_bgcnl[NP_GCN * KP_AGG];
__device__ __align__(16) __nv_bfloat16 g_bg1h [NP_G1 * KP_H2];
__device__ __align__(16) __nv_bfloat16 g_bg1l [NP_G1 * KP_H2];
__device__ __align__(16) __nv_bfloat16 g_bg2h [NP_G2 * KP_H3];
__device__ __align__(16) __nv_bfloat16 g_bg2l [NP_G2 * KP_H3];

// ---------------- baseline-PTX helpers ---------------------------------------
__device__ __forceinline__ uint32_t smem_u32(const void* p) {
    uint32_t a;
    asm("{ .reg .u64 t; cvta.to.shared.u64 t, %1; cvt.u32.u64 %0, t; }" : "=r"(a) : "l"(p));
    return a;
}
__device__ __forceinline__ void cp16(uint32_t dst, const void* src) {
    asm volatile("cp.async.cg.shared.global [%0], [%1], 16;" :: "r"(dst), "l"(src));
}
__device__ __forceinline__ void cp_commit() { asm volatile("cp.async.commit_group;"); }
template<int N> __device__ __forceinline__ void cp_wait() {
    asm volatile("cp.async.wait_group %0;" :: "n"(N));
}
__device__ __forceinline__ void ldsm4(uint32_t* r, uint32_t addr) {
    asm volatile("ldmatrix.sync.aligned.m8n8.x4.shared.b16 {%0,%1,%2,%3}, [%4];"
        : "=r"(r[0]), "=r"(r[1]), "=r"(r[2]), "=r"(r[3]) : "r"(addr));
}
__device__ __forceinline__ void mma_bf16(float* d, const uint32_t* a, const uint32_t* b) {
    asm volatile("mma.sync.aligned.m16n8k16.row.col.f32.bf16.bf16.f32 "
        "{%0,%1,%2,%3}, {%4,%5,%6,%7}, {%8,%9}, {%0,%1,%2,%3};"
        : "+f"(d[0]), "+f"(d[1]), "+f"(d[2]), "+f"(d[3])
        : "r"(a[0]), "r"(a[1]), "r"(a[2]), "r"(a[3]), "r"(b[0]), "r"(b[1]));
}

// ---------------- misc ---------------------------------------------------------
__device__ __forceinline__ void edge_sd(const int* ei, int e, int& s, int& d) {
    if (e < N_EDGES) { s = ei[e]; d = ei[N_EDGES + e]; }
    else             { s = d = e - N_EDGES; }
}
__device__ __forceinline__ float leaky(float v, float sl) { return v >= 0.f ? v : sl * v; }

// ---------------- CSR build ----------------------------------------------------
__global__ void zero_small_kernel() {
    int i = blockIdx.x * blockDim.x + threadIdx.x;
    if (i < N_NODES) { g_deg_i[i] = 0; g_fill[i] = 0; }
}
__global__ void deg_kernel(const int* __restrict__ ei) {
    int e = blockIdx.x * blockDim.x + threadIdx.x;
    if (e >= E_TOT) return;
    int s, d; edge_sd(ei, e, s, d);
    atomicAdd(&g_deg_i[d], 1);
}
__global__ void scan_kernel() {   // single block, 1024 threads
    __shared__ int sm[1024];
    int tid = threadIdx.x;
    int base = tid * 10;
    int local[10]; int sum = 0;
    #pragma unroll
    for (int i = 0; i < 10; i++) {
        int v = (base + i < N_NODES) ? g_deg_i[base + i] : 0;
        local[i] = sum; sum += v;
    }
    sm[tid] = sum; __syncthreads();
    for (int off = 1; off < 1024; off <<= 1) {
        int v = (tid >= off) ? sm[tid - off] : 0;
        __syncthreads();
        sm[tid] += v;
        __syncthreads();
    }
    int pre = (tid > 0) ? sm[tid - 1] : 0;
    #pragma unroll
    for (int i = 0; i < 10; i++)
        if (base + i < N_NODES) g_rowptr[base + i] = pre + local[i];
    if (tid == 1023) g_rowptr[N_NODES] = sm[1023];
}
__global__ void fill_kernel(const int* __restrict__ ei) {
    int e = blockIdx.x * blockDim.x + threadIdx.x;
    if (e >= E_TOT) return;
    int s, d; edge_sd(ei, e, s, d);
    int pos = atomicAdd(&g_fill[d], 1);
    int o = g_rowptr[d] + pos;
    g_csr_src[o] = s;
    g_csr_eid[o] = e;
}
__global__ void dinv_kernel() {
    int i = blockIdx.x * blockDim.x + threadIdx.x;
    if (i < N_NODES) g_dinv[i] = rsqrtf(fmaxf((float)g_deg_i[i], 1.f));
}

// ---------------- bf16 hi/lo splits --------------------------------------------
__global__ void cvtA_kernel(const float* __restrict__ in,
                            __nv_bfloat16* __restrict__ hi, __nv_bfloat16* __restrict__ lo,
                            int K, int Kp, int total) {
    int idx = blockIdx.x * blockDim.x + threadIdx.x;
    if (idx >= total) return;
    int r = idx / Kp, c = idx - r * Kp;
    float v = (r < N_NODES && c < K) ? in[(long)r * K + c] : 0.f;
    __nv_bfloat16 h = __float2bfloat16(v);
    hi[idx] = h;
    lo[idx] = __float2bfloat16(v - __bfloat162float(h));
}
__global__ void cvtB_kernel(const float* __restrict__ W,
                            __nv_bfloat16* __restrict__ hi, __nv_bfloat16* __restrict__ lo,
                            int K, int Nn, int Kp, int total) {
    int idx = blockIdx.x * blockDim.x + threadIdx.x;
    if (idx >= total) return;
    int n = idx / Kp, k = idx - n * Kp;
    float v = (k < K && n < Nn) ? W[(long)k * Nn + n] : 0.f;
    __nv_bfloat16 h = __float2bfloat16(v);
    hi[idx] = h;
    lo[idx] = __float2bfloat16(v - __bfloat162float(h));
}

// ---------------- HMMA GEMM ------------------------------------------------------
#define TSTRIDE  80
#define A_LO_OFF 10240
#define B_HI_OFF 20480
#define B_LO_OFF 30720
#define STAGE_SZ 40960
#define GEMM_SMEM (3 * STAGE_SZ)

__device__ __forceinline__ void fill_stage(uint32_t st,
        const __nv_bfloat16* __restrict__ Ah, const __nv_bfloat16* __restrict__ Al,
        const __nv_bfloat16* __restrict__ Bh, const __nv_bfloat16* __restrict__ Bl,
        int m0, int n0, int Kp, int k0, int tid) {
    #pragma unroll
    for (int i = 0; i < 2; i++) {
        int lin = tid + i * 256;
        int r = lin >> 2, cc = lin & 3;
        uint32_t d = st + r * TSTRIDE + cc * 16;
        long aoff = (long)(m0 + r) * Kp + k0;
        long boff = (long)(n0 + r) * Kp + k0;
        cp16(d,            (const char*)(Ah + aoff) + cc * 16);
        cp16(d + A_LO_OFF, (const char*)(Al + aoff) + cc * 16);
        cp16(d + B_HI_OFF, (const char*)(Bh + boff) + cc * 16);
        cp16(d + B_LO_OFF, (const char*)(Bl + boff) + cc * 16);
    }
    cp_commit();
}

template<bool BIAS, bool ACT, bool SPLIT>
__global__ __launch_bounds__(256, 1)
void mma_gemm(const __nv_bfloat16* __restrict__ Ah, const __nv_bfloat16* __restrict__ Al,
              const __nv_bfloat16* __restrict__ Bh, const __nv_bfloat16* __restrict__ Bl,
              const float* __restrict__ bias, float* __restrict__ C,
              __nv_bfloat16* __restrict__ Sh, __nv_bfloat16* __restrict__ Sl,
              int Kp, int chunks, int Nreal, int ldC) {
    extern __shared__ char smem[];
    const uint32_t tile0 = smem_u32(smem);
    const int tid = threadIdx.x, wid = tid >> 5, lane = tid & 31;
    const int m0 = blockIdx.y * 128, n0 = blockIdx.x * 128;
    const int mwoff = (wid >> 1) * 32, nwoff = (wid & 1) * 64;

    const int mat = lane >> 3, mrow = lane & 7;
    uint32_t a_off[2], b_off[4];
    #pragma unroll
    for (int ti = 0; ti < 2; ti++)
        a_off[ti] = (uint32_t)((mwoff + ti * 16 + ((mat & 1) << 3) + mrow) * TSTRIDE
                               + (mat >> 1) * 16);
    #pragma unroll
    for (int nt = 0; nt < 4; nt++)
        b_off[nt] = (uint32_t)((nwoff + nt * 16 + ((mat >> 1) << 3) + mrow) * TSTRIDE
                               + (mat & 1) * 16);

    float acc[2][8][4] = {};

    fill_stage(tile0, Ah, Al, Bh, Bl, m0, n0, Kp, 0, tid);
    if (chunks > 1) fill_stage(tile0 + STAGE_SZ, Ah, Al, Bh, Bl, m0, n0, Kp, 32, tid);

    for (int c = 0; c < chunks; c++) {
        if (c + 1 < chunks) cp_wait<1>(); else cp_wait<0>();
        __syncthreads();
        if (c + 2 < chunks)
            fill_stage(tile0 + ((c + 2) % 3) * STAGE_SZ, Ah, Al, Bh, Bl,
                       m0, n0, Kp, (c + 2) * 32, tid);
        uint32_t sb = tile0 + (c % 3) * STAGE_SZ;
        #pragma unroll
        for (int kh = 0; kh < 2; kh++) {
            uint32_t ah[2][4], al[2][4], bh[4][4], bl[4][4];
            #pragma unroll
            for (int ti = 0; ti < 2; ti++) {
                ldsm4(ah[ti], sb + a_off[ti] + kh * 32);
                ldsm4(al[ti], sb + A_LO_OFF + a_off[ti] + kh * 32);
            }
            #pragma unroll
            for (int nt = 0; nt < 4; nt++) {
                ldsm4(bh[nt], sb + B_HI_OFF + b_off[nt] + kh * 32);
                ldsm4(bl[nt], sb + B_LO_OFF + b_off[nt] + kh * 32);
            }
            #pragma unroll
            for (int ti = 0; ti < 2; ti++)
                #pragma unroll
                for (int nt = 0; nt < 8; nt++) {
                    const uint32_t* ph = &bh[nt >> 1][(nt & 1) * 2];
                    const uint32_t* pl = &bl[nt >> 1][(nt & 1) * 2];
                    mma_bf16(acc[ti][nt], ah[ti], ph);
                    mma_bf16(acc[ti][nt], ah[ti], pl);
                    mma_bf16(acc[ti][nt], al[ti], ph);
                }
        }
    }

    const int lr = lane >> 2, lc = (lane & 3) * 2;
    #pragma unroll
    for (int ti = 0; ti < 2; ti++)
        #pragma unroll
        for (int rp = 0; rp < 2; rp++) {
            int gr = m0 + mwoff + ti * 16 + rp * 8 + lr;
            if (gr >= N_NODES) continue;
            if (!SPLIT) {
                float* crow = C + (long)gr * ldC;
                #pragma unroll
                for (int nt = 0; nt < 8; nt++) {
                    int gc = n0 + nwoff + nt * 8 + lc;
                    float v0 = acc[ti][nt][rp * 2 + 0];
                    float v1 = acc[ti][nt][rp * 2 + 1];
                    if (gc < Nreal) {
                        if (BIAS) v0 += bias[gc];
                        if (ACT)  v0 = leaky(v0, 0.01f);
                        crow[gc] = v0;
                    }
                    if (gc + 1 < Nreal) {
                        if (BIAS) v1 += bias[gc + 1];
                        if (ACT)  v1 = leaky(v1, 0.01f);
                        crow[gc + 1] = v1;
                    }
                }
            } else {
                __nv_bfloat16* hr = Sh + (long)gr * ldC;
                __nv_bfloat16* lrw = Sl + (long)gr * ldC;
                #pragma unroll
                for (int nt = 0; nt < 8; nt++) {
                    int gc = n0 + nwoff + nt * 8 + lc;
                    if (gc >= ldC) continue;     // Nreal/ldC both even -> pairwise safe
                    float v0 = 0.f, v1 = 0.f;
                    if (gc < Nreal) {
                        v0 = acc[ti][nt][rp * 2 + 0];
                        if (BIAS) v0 += bias[gc];
                        if (ACT)  v0 = leaky(v0, 0.01f);
                    }
                    if (gc + 1 < Nreal) {
                        v1 = acc[ti][nt][rp * 2 + 1];
                        if (BIAS) v1 += bias[gc + 1];
                        if (ACT)  v1 = leaky(v1, 0.01f);
                    }
                    __nv_bfloat16 h0 = __float2bfloat16(v0);
                    __nv_bfloat16 h1 = __float2bfloat16(v1);
                    __nv_bfloat162 hp; hp.x = h0; hp.y = h1;
                    __nv_bfloat162 lp;
                    lp.x = __float2bfloat16(v0 - __bfloat162float(h0));
                    lp.y = __float2bfloat16(v1 - __bfloat162float(h1));
                    *(__nv_bfloat162*)(hr + gc) = hp;
                    *(__nv_bfloat162*)(lrw + gc) = lp;
                }
            }
        }
}

// ---------------- attention coefficients ------------------------------------
__global__ void attn_kernel(const float* __restrict__ att_src,
                            const float* __restrict__ att_dst) {
    int idx = blockIdx.x * blockDim.x + threadIdx.x;
    if (idx >= N_NODES * HEADS) return;
    int n = idx / HEADS, h = idx % HEADS;
    const float* xr = g_xt + n * D1 + h * FHEAD;
    const float* as = att_src + h * FHEAD;
    const float* ad = att_dst + h * FHEAD;
    float s = 0.f, d = 0.f;
    #pragma unroll
    for (int f = 0; f < FHEAD; f++) { float v = xr[f]; s += v * as[f]; d += v * ad[f]; }
    g_as[idx] = s; g_ad[idx] = d;
}

// ---------------- per-edge softmax numerators ---------------------------------
// max-subtraction skipped: |e| bounded (0.05-scaled weights); softmax shift-invariant.
__global__ void w_kernel(const int* __restrict__ ei) {
    int e = blockIdx.x * blockDim.x + threadIdx.x;
    if (e >= E_TOT) return;
    int s, d; edge_sd(ei, e, s, d);
    #pragma unroll
    for (int h = 0; h < HEADS; h++) {
        float v = g_as[s * HEADS + h] + g_ad[d * HEADS + h];
        g_w[e * HEADS + h] = expf(leaky(v, 0.2f));
    }
}

// ---------------- GAT gather: warp per destination node ----------------------
__global__ void gat_gather_kernel(const float* __restrict__ b_gat) {
    int gw = (blockIdx.x * blockDim.x + threadIdx.x) >> 5;
    int lane = threadIdx.x & 31;
    int wl = threadIdx.x >> 5;
    __shared__ float sal[8][HEADS];
    if (gw >= N_NODES) return;
    int beg = g_rowptr[gw], end = g_rowptr[gw + 1];

    // softmax denominator per head (lanes 0-9)
    float ssum = 0.f;
    if (lane < HEADS)
        for (int i = beg; i < end; i++) ssum += g_w[g_csr_eid[i] * HEADS + lane];
    float inv = (lane < HEADS) ? 1.f / fmaxf(ssum, 1e-16f) : 0.f;

    float4 acc[6];
    #pragma unroll
    for (int j = 0; j < 6; j++) acc[j] = make_float4(0.f, 0.f, 0.f, 0.f);

    for (int i = beg; i < end; i++) {
        int eid = g_csr_eid[i], src = g_csr_src[i];
        if (lane < HEADS) sal[wl][lane] = g_w[eid * HEADS + lane] * inv;
        __syncwarp();
        const float4* xs = (const float4*)g_xt + src * (D1 / 4);
        #pragma unroll
        for (int j = 0; j < 6; j++) {
            int f4 = lane + 32 * j;
            if (f4 < D1 / 4) {
                float4 v = xs[f4];
                int f = 4 * f4;
                acc[j].x += v.x * sal[wl][ f      / FHEAD];
                acc[j].y += v.y * sal[wl][(f + 1) / FHEAD];
                acc[j].z += v.z * sal[wl][(f + 2) / FHEAD];
                acc[j].w += v.w * sal[wl][(f + 3) / FHEAD];
            }
        }
        __syncwarp();
    }

    const float4* b4 = (const float4*)b_gat;
    float4* hd = (float4*)g_h1 + gw * (D1 / 4);
    #pragma unroll
    for (int j = 0; j < 6; j++) {
        int f4 = lane + 32 * j;
        if (f4 < D1 / 4) {
            float4 b = b4[f4], r;
            r.x = leaky(acc[j].x + b.x, 0.01f);
            r.y = leaky(acc[j].y + b.y, 0.01f);
            r.z = leaky(acc[j].z + b.z, 0.01f);
            r.w = leaky(acc[j].w + b.w, 0.01f);
            hd[f4] = r;
        }
    }
}

// ---------------- GCN gather: warp per node, writes bf16 hi/lo directly ------
__global__ void gcn_gather_kernel() {
    int gw = (blockIdx.x * blockDim.x + threadIdx.x) >> 5;
    int lane = threadIdx.x & 31;
    if (gw >= N_NODES) return;
    int beg = g_rowptr[gw], end = g_rowptr[gw + 1];
    float dd = g_dinv[gw];

    float4 acc[6];
    #pragma unroll
    for (int j = 0; j < 6; j++) acc[j] = make_float4(0.f, 0.f, 0.f, 0.f);

    for (int i = beg; i < end; i++) {
        int src = g_csr_src[i];
        float nm = dd * g_dinv[src];
        const float4* hs = (const float4*)g_h1 + src * (D1 / 4);
        #pragma unroll
        for (int j = 0; j < 6; j++) {
            int f4 = lane + 32 * j;
            if (f4 < D1 / 4) {
                float4 v = hs[f4];
                acc[j].x += v.x * nm;
                acc[j].y += v.y * nm;
                acc[j].z += v.z * nm;
                acc[j].w += v.w * nm;
            }
        }
    }

    __nv_bfloat16* hr = g_aah + (long)gw * KP_AGG;
    __nv_bfloat16* lr = g_aal + (long)gw * KP_AGG;
    #pragma unroll
    for (int j = 0; j < 6; j++) {
        int f4 = lane + 32 * j;
        if (f4 < D1 / 4) {
            float vv[4] = {acc[j].x, acc[j].y, acc[j].z, acc[j].w};
            __nv_bfloat162 hp0, hp1, lp0, lp1;
            __nv_bfloat16 h0 = __float2bfloat16(vv[0]);
            __nv_bfloat16 h1 = __float2bfloat16(vv[1]);
            __nv_bfloat16 h2 = __float2bfloat16(vv[2]);
            __nv_bfloat16 h3 = __float2bfloat16(vv[3]);
            hp0.x = h0; hp0.y = h1; hp1.x = h2; hp1.y = h3;
            lp0.x = __float2bfloat16(vv[0] - __bfloat162float(h0));
            lp0.y = __float2bfloat16(vv[1] - __bfloat162float(h1));
            lp1.x = __float2bfloat16(vv[2] - __bfloat162float(h2));
            lp1.y = __float2bfloat16(vv[3] - __bfloat162float(h3));
            int c = 4 * f4;
            ((__nv_bfloat162*)(hr + c))[0] = hp0;
            ((__nv_bfloat162*)(hr + c))[1] = hp1;
            ((__nv_bfloat162*)(lr + c))[0] = lp0;
            ((__nv_bfloat162*)(lr + c))[1] = lp1;
        }
    }
    // zero the K padding columns [D1, KP_AGG)
    for (int c = D1 + lane; c < KP_AGG; c += 32) {
        hr[c] = __float2bfloat16(0.f);
        lr[c] = __float2bfloat16(0.f);
    }
}

// ---------------- tail ----------------------------------------------------------
__global__ void tail_kernel(const float* __restrict__ W1, const float* __restrict__ b1,
                            const float* __restrict__ W2, const float* __restrict__ b2,
                            const float* __restrict__ W3, const float* __restrict__ b3,
                            float* __restrict__ out) {
    int gw = (blockIdx.x * blockDim.x + threadIdx.x) >> 5;
    int lane = threadIdx.x & 31;
    if (gw >= N_NODES) return;
    float v0 = g_h4[gw * 64 + lane];
    float v1 = g_h4[gw * 64 + 32 + lane];
    float s = b1[lane];
    #pragma unroll
    for (int k = 0; k < 32; k++) s += __shfl_sync(0xffffffffu, v0, k) * W1[k * 32 + lane];
    #pragma unroll
    for (int k = 0; k < 32; k++) s += __shfl_sync(0xffffffffu, v1, k) * W1[(k + 32) * 32 + lane];
    float u = leaky(s, 0.01f);
    int j = lane & 15;
    float s2 = b2[j];
    #pragma unroll
    for (int k = 0; k < 32; k++) s2 += __shfl_sync(0xffffffffu, u, k) * W2[k * 16 + j];
    float t = leaky(s2, 0.01f);
    float o = (lane < 16) ? t * W3[lane] : 0.f;
    #pragma unroll
    for (int off = 8; off > 0; off >>= 1) o += __shfl_down_sync(0xffffffffu, o, off);
    if (lane == 0) out[gw] = o + b3[0];
}

// ---------------- launch ----------------------------------------------------------
extern "C" void kernel_launch(void* const* d_in, const int* in_sizes, int n_in,
                              void* d_out, int out_size) {
    const float* x     = (const float*)d_in[0];
    const int*   ei    = (const int*)  d_in[1];
    const float* W_gat = (const float*)d_in[2];
    const float* att_s = (const float*)d_in[3];
    const float* att_d = (const float*)d_in[4];
    const float* b_gat = (const float*)d_in[5];
    const float* W_gcn = (const float*)d_in[6];
    const float* b_gcn = (const float*)d_in[7];
    const float* W_g1  = (const float*)d_in[8];
    const float* b_g1  = (const float*)d_in[9];
    const float* W_g2  = (const float*)d_in[10];
    const float* b_g2  = (const float*)d_in[11];
    const float* W_fc1 = (const float*)d_in[12];
    const float* b_fc1 = (const float*)d_in[13];
    const float* W_fc2 = (const float*)d_in[14];
    const float* b_fc2 = (const float*)d_in[15];
    const float* W_out = (const float*)d_in[16];
    const float* b_out = (const float*)d_in[17];
    float* out = (float*)d_out;
    (void)in_sizes; (void)n_in; (void)out_size;

    cudaFuncSetAttribute(mma_gemm<false, false, false>, cudaFuncAttributeMaxDynamicSharedMemorySize, GEMM_SMEM);
    cudaFuncSetAttribute(mma_gemm<true, true, true>,    cudaFuncAttributeMaxDynamicSharedMemorySize, GEMM_SMEM);
    cudaFuncSetAttribute(mma_gemm<true, true, false>,   cudaFuncAttributeMaxDynamicSharedMemorySize, GEMM_SMEM);

    #define SYMADDR(p, s) float* p; cudaGetSymbolAddress((void**)&p, s)
    SYMADDR(p_xt, g_xt); SYMADDR(p_h4, g_h4);
    #define BFADDR(p, s) __nv_bfloat16* p; cudaGetSymbolAddress((void**)&p, s)
    BFADDR(axh, g_axh); BFADDR(axl, g_axl);
    BFADDR(aah, g_aah); BFADDR(aal, g_aal);
    BFADDR(a2h, g_a2h); BFADDR(a2l, g_a2l);
    BFADDR(a3h, g_a3h); BFADDR(a3l, g_a3l);
    BFADDR(bgath, g_bgath); BFADDR(bgatl, g_bgatl);
    BFADDR(bgcnh, g_bgcnh); BFADDR(bgcnl, g_bgcnl);
    BFADDR(bg1h, g_bg1h); BFADDR(bg1l, g_bg1l);
    BFADDR(bg2h, g_bg2h); BFADDR(bg2l, g_bg2l);

    // CSR build (independent of GEMMs)
    zero_small_kernel<<<(N_NODES + 255) / 256, 256>>>();
    deg_kernel<<<(E_TOT + 255) / 256, 256>>>(ei);
    scan_kernel<<<1, 1024>>>();
    fill_kernel<<<(E_TOT + 255) / 256, 256>>>(ei);
    dinv_kernel<<<(N_NODES + 255) / 256, 256>>>();

    // weight + input splits
    cvtB_kernel<<<(NP_GAT * KP_X + 255) / 256, 256>>>(W_gat, bgath, bgatl, F_IN, D1, KP_X, NP_GAT * KP_X);
    cvtB_kernel<<<(NP_GCN * KP_AGG + 255) / 256, 256>>>(W_gcn, bgcnh, bgcnl, D1, D2, KP_AGG, NP_GCN * KP_AGG);
    cvtB_kernel<<<(NP_G1 * KP_H2 + 255) / 256, 256>>>(W_g1, bg1h, bg1l, D2, D3, KP_H2, NP_G1 * KP_H2);
    cvtB_kernel<<<(NP_G2 * KP_H3 + 255) / 256, 256>>>(W_g2, bg2h, bg2l, D3, D4, KP_H3, NP_G2 * KP_H3);
    cvtA_kernel<<<(M_PAD * KP_X + 255) / 256, 256>>>(x, axh, axl, F_IN, KP_X, M_PAD * KP_X);

    // GAT linear: xt = x @ W_gat
    mma_gemm<false, false, false><<<dim3(NP_GAT / 128, M_PAD / 128), 256, GEMM_SMEM>>>(
        axh, axl, bgath, bgatl, nullptr, p_xt, nullptr, nullptr, KP_X, KP_X / 32, D1, D1);

    attn_kernel<<<(N_NODES * HEADS + 255) / 256, 256>>>(att_s, att_d);
    w_kernel<<<(E_TOT + 255) / 256, 256>>>(ei);
    gat_gather_kernel<<<(N_NODES * 32 + 255) / 256, 256>>>(b_gat);
    gcn_gather_kernel<<<(N_NODES * 32 + 255) / 256, 256>>>();

    // GCN linear -> split bf16 directly
    mma_gemm<true, true, true><<<dim3(NP_GCN / 128, M_PAD / 128), 256, GEMM_SMEM>>>(
        aah, aal, bgcnh, bgcnl, b_gcn, nullptr, a2h, a2l, KP_AGG, KP_AGG / 32, D2, KP_H2);
    // g1 -> split bf16 directly
    mma_gemm<true, true, true><<<dim3(NP_G1 / 128, M_PAD / 128), 256, GEMM_SMEM>>>(
        a2h, a2l, bg1h, bg1l, b_g1, nullptr, a3h, a3l, KP_H2, KP_H2 / 32, D3, KP_H3);
    // g2 -> fp32 h4
    mma_gemm<true, true, false><<<dim3(NP_G2 / 128, M_PAD / 128), 256, GEMM_SMEM>>>(
        a3h, a3l, bg2h, bg2l, b_g2, p_h4, nullptr, nullptr, KP_H3, KP_H3 / 32, D4, D4);

    tail_kernel<<<(N_NODES * 32 + 255) / 256, 256>>>(
        W_fc1, b_fc1, W_fc2, b_fc2, W_out, b_out, out);
}

// round 5
// speedup vs baseline: 2.6902x; 1.2734x over previous
#include <cuda_runtime.h>
#include <cuda_fp16.h>
#include <math.h>
#include <stdint.h>

#define N_NODES 10000
#define N_EDGES 120000
#define E_TOT   130000
#define F_IN    66
#define HEADS   10
#define FHEAD   66
#define D1      660
#define D2      1320
#define D3      1000
#define D4      64
#define M_PAD   10112        // 79 * 128

#define KP_X    96
#define KP_AGG  704
#define KP_H2   1344
#define KP_H3   1024
#define NP_GAT  768
#define NP_GCN  1408
#define NP_G1   1024
#define NP_G2   128

// ---------------- fp32 scratch ----------------------------------------------
__device__ __align__(16) float g_xt [N_NODES * D1];
__device__             float g_as [N_NODES * HEADS];
__device__             float g_ad [N_NODES * HEADS];
__device__             float g_dinv[N_NODES];
__device__ __align__(16) float g_h1 [N_NODES * D1];
__device__ __align__(16) float g_h4 [N_NODES * D4];
__device__ __align__(16) float g_w  [E_TOT * HEADS];

// ---------------- CSR over destination --------------------------------------
__device__ int g_deg_i [N_NODES];
__device__ int g_fill  [N_NODES];
__device__ int g_rowptr[N_NODES + 1];
__device__ int g_csr_src[E_TOT];
__device__ int g_csr_eid[E_TOT];

// ---------------- fp16 split buffers (A: hi+lo, B: hi only) ------------------
__device__ __align__(16) __half g_axh [M_PAD * KP_X];
__device__ __align__(16) __half g_axl [M_PAD * KP_X];
__device__ __align__(16) __half g_aah [M_PAD * KP_AGG];
__device__ __align__(16) __half g_aal [M_PAD * KP_AGG];
__device__ __align__(16) __half g_a2h [M_PAD * KP_H2];
__device__ __align__(16) __half g_a2l [M_PAD * KP_H2];
__device__ __align__(16) __half g_a3h [M_PAD * KP_H3];
__device__ __align__(16) __half g_a3l [M_PAD * KP_H3];
__device__ __align__(16) __half g_bgat[NP_GAT * KP_X];
__device__ __align__(16) __half g_bgcn[NP_GCN * KP_AGG];
__device__ __align__(16) __half g_bg1 [NP_G1 * KP_H2];
__device__ __align__(16) __half g_bg2 [NP_G2 * KP_H3];

// ---------------- baseline-PTX helpers ---------------------------------------
__device__ __forceinline__ uint32_t smem_u32(const void* p) {
    uint32_t a;
    asm("{ .reg .u64 t; cvta.to.shared.u64 t, %1; cvt.u32.u64 %0, t; }" : "=r"(a) : "l"(p));
    return a;
}
__device__ __forceinline__ void cp16(uint32_t dst, const void* src) {
    asm volatile("cp.async.cg.shared.global [%0], [%1], 16;" :: "r"(dst), "l"(src));
}
__device__ __forceinline__ void cp_commit() { asm volatile("cp.async.commit_group;"); }
template<int N> __device__ __forceinline__ void cp_wait() {
    asm volatile("cp.async.wait_group %0;" :: "n"(N));
}
__device__ __forceinline__ void ldsm4(uint32_t* r, uint32_t addr) {
    asm volatile("ldmatrix.sync.aligned.m8n8.x4.shared.b16 {%0,%1,%2,%3}, [%4];"
        : "=r"(r[0]), "=r"(r[1]), "=r"(r[2]), "=r"(r[3]) : "r"(addr));
}
__device__ __forceinline__ void mma_f16(float* d, const uint32_t* a, const uint32_t* b) {
    asm volatile("mma.sync.aligned.m16n8k16.row.col.f32.f16.f16.f32 "
        "{%0,%1,%2,%3}, {%4,%5,%6,%7}, {%8,%9}, {%0,%1,%2,%3};"
        : "+f"(d[0]), "+f"(d[1]), "+f"(d[2]), "+f"(d[3])
        : "r"(a[0]), "r"(a[1]), "r"(a[2]), "r"(a[3]), "r"(b[0]), "r"(b[1]));
}

// ---------------- misc ---------------------------------------------------------
__device__ __forceinline__ void edge_sd(const int* ei, int e, int& s, int& d) {
    if (e < N_EDGES) { s = ei[e]; d = ei[N_EDGES + e]; }
    else             { s = d = e - N_EDGES; }
}
__device__ __forceinline__ float leaky(float v, float sl) { return v >= 0.f ? v : sl * v; }

// ---------------- CSR build ----------------------------------------------------
__global__ void zero_small_kernel() {
    int i = blockIdx.x * blockDim.x + threadIdx.x;
    if (i < N_NODES) { g_deg_i[i] = 0; g_fill[i] = 0; }
}
__global__ void deg_kernel(const int* __restrict__ ei) {
    int e = blockIdx.x * blockDim.x + threadIdx.x;
    if (e >= E_TOT) return;
    int s, d; edge_sd(ei, e, s, d);
    atomicAdd(&g_deg_i[d], 1);
}
__global__ void scan_kernel() {   // single block, 1024 threads
    __shared__ int sm[1024];
    int tid = threadIdx.x;
    int base = tid * 10;
    int local[10]; int sum = 0;
    #pragma unroll
    for (int i = 0; i < 10; i++) {
        int v = (base + i < N_NODES) ? g_deg_i[base + i] : 0;
        local[i] = sum; sum += v;
    }
    sm[tid] = sum; __syncthreads();
    for (int off = 1; off < 1024; off <<= 1) {
        int v = (tid >= off) ? sm[tid - off] : 0;
        __syncthreads();
        sm[tid] += v;
        __syncthreads();
    }
    int pre = (tid > 0) ? sm[tid - 1] : 0;
    #pragma unroll
    for (int i = 0; i < 10; i++)
        if (base + i < N_NODES) g_rowptr[base + i] = pre + local[i];
    if (tid == 1023) g_rowptr[N_NODES] = sm[1023];
}
__global__ void fill_kernel(const int* __restrict__ ei) {
    int e = blockIdx.x * blockDim.x + threadIdx.x;
    if (e >= E_TOT) return;
    int s, d; edge_sd(ei, e, s, d);
    int pos = atomicAdd(&g_fill[d], 1);
    int o = g_rowptr[d] + pos;
    g_csr_src[o] = s;
    g_csr_eid[o] = e;
}
__global__ void dinv_kernel() {
    int i = blockIdx.x * blockDim.x + threadIdx.x;
    if (i < N_NODES) g_dinv[i] = rsqrtf(fmaxf((float)g_deg_i[i], 1.f));
}

// ---------------- fp16 splits ----------------------------------------------------
__global__ void cvtA_kernel(const float* __restrict__ in,
                            __half* __restrict__ hi, __half* __restrict__ lo,
                            int K, int Kp, int total) {
    int idx = blockIdx.x * blockDim.x + threadIdx.x;
    if (idx >= total) return;
    int r = idx / Kp, c = idx - r * Kp;
    float v = (r < N_NODES && c < K) ? in[(long)r * K + c] : 0.f;
    __half h = __float2half_rn(v);
    hi[idx] = h;
    lo[idx] = __float2half_rn(v - __half2float(h));
}
__global__ void cvtB_kernel(const float* __restrict__ W, __half* __restrict__ hi,
                            int K, int Nn, int Kp, int total) {
    int idx = blockIdx.x * blockDim.x + threadIdx.x;
    if (idx >= total) return;
    int n = idx / Kp, k = idx - n * Kp;
    float v = (k < K && n < Nn) ? W[(long)k * Nn + n] : 0.f;
    hi[idx] = __float2half_rn(v);
}

// ---------------- HMMA GEMM (fp16 2-term split, 4-stage cp.async) -----------------
#define TSTRIDE  80
#define A_LO_OFF 10240
#define B_HI_OFF 20480
#define STAGE_SZ 30720
#define GEMM_SMEM (4 * STAGE_SZ)

__device__ __forceinline__ void fill_stage(uint32_t st,
        const __half* __restrict__ Ah, const __half* __restrict__ Al,
        const __half* __restrict__ Bh,
        int m0, int n0, int Kp, int k0, int tid) {
    #pragma unroll
    for (int i = 0; i < 2; i++) {
        int lin = tid + i * 256;
        int r = lin >> 2, cc = lin & 3;
        uint32_t d = st + r * TSTRIDE + cc * 16;
        long aoff = (long)(m0 + r) * Kp + k0;
        long boff = (long)(n0 + r) * Kp + k0;
        cp16(d,            (const char*)(Ah + aoff) + cc * 16);
        cp16(d + A_LO_OFF, (const char*)(Al + aoff) + cc * 16);
        cp16(d + B_HI_OFF, (const char*)(Bh + boff) + cc * 16);
    }
    cp_commit();
}

template<bool BIAS, bool ACT, bool SPLIT>
__global__ __launch_bounds__(256, 1)
void mma_gemm(const __half* __restrict__ Ah, const __half* __restrict__ Al,
              const __half* __restrict__ Bh,
              const float* __restrict__ bias, float* __restrict__ C,
              __half* __restrict__ Sh, __half* __restrict__ Sl,
              int Kp, int chunks, int Nreal, int ldC) {
    extern __shared__ char smem[];
    const uint32_t tile0 = smem_u32(smem);
    const int tid = threadIdx.x, wid = tid >> 5, lane = tid & 31;
    const int m0 = blockIdx.y * 128, n0 = blockIdx.x * 128;
    const int mwoff = (wid >> 1) * 32, nwoff = (wid & 1) * 64;

    const int mat = lane >> 3, mrow = lane & 7;
    uint32_t a_off[2], b_off[4];
    #pragma unroll
    for (int ti = 0; ti < 2; ti++)
        a_off[ti] = (uint32_t)((mwoff + ti * 16 + ((mat & 1) << 3) + mrow) * TSTRIDE
                               + (mat >> 1) * 16);
    #pragma unroll
    for (int nt = 0; nt < 4; nt++)
        b_off[nt] = (uint32_t)((nwoff + nt * 16 + ((mat >> 1) << 3) + mrow) * TSTRIDE
                               + (mat & 1) * 16);

    float acc[2][8][4] = {};

    // prologue: fill up to 3 stages
    fill_stage(tile0, Ah, Al, Bh, m0, n0, Kp, 0, tid);
    if (chunks > 1) fill_stage(tile0 + STAGE_SZ, Ah, Al, Bh, m0, n0, Kp, 32, tid);
    if (chunks > 2) fill_stage(tile0 + 2 * STAGE_SZ, Ah, Al, Bh, m0, n0, Kp, 64, tid);

    for (int c = 0; c < chunks; c++) {
        if (c + 2 < chunks)      cp_wait<2>();
        else if (c + 1 < chunks) cp_wait<1>();
        else                     cp_wait<0>();
        __syncthreads();
        if (c + 3 < chunks)
            fill_stage(tile0 + ((c + 3) & 3) * STAGE_SZ, Ah, Al, Bh,
                       m0, n0, Kp, (c + 3) * 32, tid);
        uint32_t sb = tile0 + (c & 3) * STAGE_SZ;
        #pragma unroll
        for (int kh = 0; kh < 2; kh++) {
            uint32_t ah[2][4], al[2][4], bh[4][4];
            #pragma unroll
            for (int ti = 0; ti < 2; ti++) {
                ldsm4(ah[ti], sb + a_off[ti] + kh * 32);
                ldsm4(al[ti], sb + A_LO_OFF + a_off[ti] + kh * 32);
            }
            #pragma unroll
            for (int nt = 0; nt < 4; nt++)
                ldsm4(bh[nt], sb + B_HI_OFF + b_off[nt] + kh * 32);
            #pragma unroll
            for (int ti = 0; ti < 2; ti++)
                #pragma unroll
                for (int nt = 0; nt < 8; nt++) {
                    const uint32_t* pb = &bh[nt >> 1][(nt & 1) * 2];
                    mma_f16(acc[ti][nt], ah[ti], pb);
                    mma_f16(acc[ti][nt], al[ti], pb);
                }
        }
    }

    const int lr = lane >> 2, lc = (lane & 3) * 2;
    #pragma unroll
    for (int ti = 0; ti < 2; ti++)
        #pragma unroll
        for (int rp = 0; rp < 2; rp++) {
            int gr = m0 + mwoff + ti * 16 + rp * 8 + lr;
            if (gr >= N_NODES) continue;
            if (!SPLIT) {
                float* crow = C + (long)gr * ldC;
                #pragma unroll
                for (int nt = 0; nt < 8; nt++) {
                    int gc = n0 + nwoff + nt * 8 + lc;
                    float v0 = acc[ti][nt][rp * 2 + 0];
                    float v1 = acc[ti][nt][rp * 2 + 1];
                    if (gc < Nreal) {
                        if (BIAS) v0 += bias[gc];
                        if (ACT)  v0 = leaky(v0, 0.01f);
                        crow[gc] = v0;
                    }
                    if (gc + 1 < Nreal) {
                        if (BIAS) v1 += bias[gc + 1];
                        if (ACT)  v1 = leaky(v1, 0.01f);
                        crow[gc + 1] = v1;
                    }
                }
            } else {
                __half* hr = Sh + (long)gr * ldC;
                __half* lrw = Sl + (long)gr * ldC;
                #pragma unroll
                for (int nt = 0; nt < 8; nt++) {
                    int gc = n0 + nwoff + nt * 8 + lc;
                    if (gc >= ldC) continue;
                    float v0 = 0.f, v1 = 0.f;
                    if (gc < Nreal) {
                        v0 = acc[ti][nt][rp * 2 + 0];
                        if (BIAS) v0 += bias[gc];
                        if (ACT)  v0 = leaky(v0, 0.01f);
                    }
                    if (gc + 1 < Nreal) {
                        v1 = acc[ti][nt][rp * 2 + 1];
                        if (BIAS) v1 += bias[gc + 1];
                        if (ACT)  v1 = leaky(v1, 0.01f);
                    }
                    __half h0 = __float2half_rn(v0);
                    __half h1 = __float2half_rn(v1);
                    __half2 hp; hp.x = h0; hp.y = h1;
                    __half2 lp;
                    lp.x = __float2half_rn(v0 - __half2float(h0));
                    lp.y = __float2half_rn(v1 - __half2float(h1));
                    *(__half2*)(hr + gc) = hp;
                    *(__half2*)(lrw + gc) = lp;
                }
            }
        }
}

// ---------------- attention coefficients ------------------------------------
__global__ void attn_kernel(const float* __restrict__ att_src,
                            const float* __restrict__ att_dst) {
    int idx = blockIdx.x * blockDim.x + threadIdx.x;
    if (idx >= N_NODES * HEADS) return;
    int n = idx / HEADS, h = idx % HEADS;
    const float* xr = g_xt + n * D1 + h * FHEAD;
    const float* as = att_src + h * FHEAD;
    const float* ad = att_dst + h * FHEAD;
    float s = 0.f, d = 0.f;
    #pragma unroll
    for (int f = 0; f < FHEAD; f++) { float v = xr[f]; s += v * as[f]; d += v * ad[f]; }
    g_as[idx] = s; g_ad[idx] = d;
}

// ---------------- per-edge softmax numerators ---------------------------------
__global__ void w_kernel(const int* __restrict__ ei) {
    int e = blockIdx.x * blockDim.x + threadIdx.x;
    if (e >= E_TOT) return;
    int s, d; edge_sd(ei, e, s, d);
    #pragma unroll
    for (int h = 0; h < HEADS; h++) {
        float v = g_as[s * HEADS + h] + g_ad[d * HEADS + h];
        g_w[e * HEADS + h] = expf(leaky(v, 0.2f));
    }
}

// ---------------- GAT gather: warp per destination node ----------------------
__global__ void gat_gather_kernel(const float* __restrict__ b_gat) {
    int gw = (blockIdx.x * blockDim.x + threadIdx.x) >> 5;
    int lane = threadIdx.x & 31;
    int wl = threadIdx.x >> 5;
    __shared__ float sal[8][HEADS];
    if (gw >= N_NODES) return;
    int beg = g_rowptr[gw], end = g_rowptr[gw + 1];

    float ssum = 0.f;
    if (lane < HEADS)
        for (int i = beg; i < end; i++) ssum += g_w[g_csr_eid[i] * HEADS + lane];
    float inv = (lane < HEADS) ? 1.f / fmaxf(ssum, 1e-16f) : 0.f;

    float4 acc[6];
    #pragma unroll
    for (int j = 0; j < 6; j++) acc[j] = make_float4(0.f, 0.f, 0.f, 0.f);

    for (int i = beg; i < end; i++) {
        int eid = g_csr_eid[i], src = g_csr_src[i];
        if (lane < HEADS) sal[wl][lane] = g_w[eid * HEADS + lane] * inv;
        __syncwarp();
        const float4* xs = (const float4*)g_xt + src * (D1 / 4);
        #pragma unroll
        for (int j = 0; j < 6; j++) {
            int f4 = lane + 32 * j;
            if (f4 < D1 / 4) {
                float4 v = xs[f4];
                int f = 4 * f4;
                acc[j].x += v.x * sal[wl][ f      / FHEAD];
                acc[j].y += v.y * sal[wl][(f + 1) / FHEAD];
                acc[j].z += v.z * sal[wl][(f + 2) / FHEAD];
                acc[j].w += v.w * sal[wl][(f + 3) / FHEAD];
            }
        }
        __syncwarp();
    }

    const float4* b4 = (const float4*)b_gat;
    float4* hd = (float4*)g_h1 + gw * (D1 / 4);
    #pragma unroll
    for (int j = 0; j < 6; j++) {
        int f4 = lane + 32 * j;
        if (f4 < D1 / 4) {
            float4 b = b4[f4], r;
            r.x = leaky(acc[j].x + b.x, 0.01f);
            r.y = leaky(acc[j].y + b.y, 0.01f);
            r.z = leaky(acc[j].z + b.z, 0.01f);
            r.w = leaky(acc[j].w + b.w, 0.01f);
            hd[f4] = r;
        }
    }
}

// ---------------- GCN gather: warp per node, writes fp16 hi/lo directly ------
__global__ void gcn_gather_kernel() {
    int gw = (blockIdx.x * blockDim.x + threadIdx.x) >> 5;
    int lane = threadIdx.x & 31;
    if (gw >= N_NODES) return;
    int beg = g_rowptr[gw], end = g_rowptr[gw + 1];
    float dd = g_dinv[gw];

    float4 acc[6];
    #pragma unroll
    for (int j = 0; j < 6; j++) acc[j] = make_float4(0.f, 0.f, 0.f, 0.f);

    for (int i = beg; i < end; i++) {
        int src = g_csr_src[i];
        float nm = dd * g_dinv[src];
        const float4* hs = (const float4*)g_h1 + src * (D1 / 4);
        #pragma unroll
        for (int j = 0; j < 6; j++) {
            int f4 = lane + 32 * j;
            if (f4 < D1 / 4) {
                float4 v = hs[f4];
                acc[j].x += v.x * nm;
                acc[j].y += v.y * nm;
                acc[j].z += v.z * nm;
                acc[j].w += v.w * nm;
            }
        }
    }

    __half* hr = g_aah + (long)gw * KP_AGG;
    __half* lr = g_aal + (long)gw * KP_AGG;
    #pragma unroll
    for (int j = 0; j < 6; j++) {
        int f4 = lane + 32 * j;
        if (f4 < D1 / 4) {
            float vv[4] = {acc[j].x, acc[j].y, acc[j].z, acc[j].w};
            __half h0 = __float2half_rn(vv[0]);
            __half h1 = __float2half_rn(vv[1]);
            __half h2 = __float2half_rn(vv[2]);
            __half h3 = __float2half_rn(vv[3]);
            __half2 hp0, hp1, lp0, lp1;
            hp0.x = h0; hp0.y = h1; hp1.x = h2; hp1.y = h3;
            lp0.x = __float2half_rn(vv[0] - __half2float(h0));
            lp0.y = __float2half_rn(vv[1] - __half2float(h1));
            lp1.x = __float2half_rn(vv[2] - __half2float(h2));
            lp1.y = __float2half_rn(vv[3] - __half2float(h3));
            int c = 4 * f4;
            ((__half2*)(hr + c))[0] = hp0;
            ((__half2*)(hr + c))[1] = hp1;
            ((__half2*)(lr + c))[0] = lp0;
            ((__half2*)(lr + c))[1] = lp1;
        }
    }
    for (int c = D1 + lane; c < KP_AGG; c += 32) {
        hr[c] = __float2half_rn(0.f);
        lr[c] = __float2half_rn(0.f);
    }
}

// ---------------- tail ----------------------------------------------------------
__global__ void tail_kernel(const float* __restrict__ W1, const float* __restrict__ b1,
                            const float* __restrict__ W2, const float* __restrict__ b2,
                            const float* __restrict__ W3, const float* __restrict__ b3,
                            float* __restrict__ out) {
    int gw = (blockIdx.x * blockDim.x + threadIdx.x) >> 5;
    int lane = threadIdx.x & 31;
    if (gw >= N_NODES) return;
    float v0 = g_h4[gw * 64 + lane];
    float v1 = g_h4[gw * 64 + 32 + lane];
    float s = b1[lane];
    #pragma unroll
    for (int k = 0; k < 32; k++) s += __shfl_sync(0xffffffffu, v0, k) * W1[k * 32 + lane];
    #pragma unroll
    for (int k = 0; k < 32; k++) s += __shfl_sync(0xffffffffu, v1, k) * W1[(k + 32) * 32 + lane];
    float u = leaky(s, 0.01f);
    int j = lane & 15;
    float s2 = b2[j];
    #pragma unroll
    for (int k = 0; k < 32; k++) s2 += __shfl_sync(0xffffffffu, u, k) * W2[k * 16 + j];
    float t = leaky(s2, 0.01f);
    float o = (lane < 16) ? t * W3[lane] : 0.f;
    #pragma unroll
    for (int off = 8; off > 0; off >>= 1) o += __shfl_down_sync(0xffffffffu, o, off);
    if (lane == 0) out[gw] = o + b3[0];
}

// ---------------- launch ----------------------------------------------------------
extern "C" void kernel_launch(void* const* d_in, const int* in_sizes, int n_in,
                              void* d_out, int out_size) {
    const float* x     = (const float*)d_in[0];
    const int*   ei    = (const int*)  d_in[1];
    const float* W_gat = (const float*)d_in[2];
    const float* att_s = (const float*)d_in[3];
    const float* att_d = (const float*)d_in[4];
    const float* b_gat = (const float*)d_in[5];
    const float* W_gcn = (const float*)d_in[6];
    const float* b_gcn = (const float*)d_in[7];
    const float* W_g1  = (const float*)d_in[8];
    const float* b_g1  = (const float*)d_in[9];
    const float* W_g2  = (const float*)d_in[10];
    const float* b_g2  = (const float*)d_in[11];
    const float* W_fc1 = (const float*)d_in[12];
    const float* b_fc1 = (const float*)d_in[13];
    const float* W_fc2 = (const float*)d_in[14];
    const float* b_fc2 = (const float*)d_in[15];
    const float* W_out = (const float*)d_in[16];
    const float* b_out = (const float*)d_in[17];
    float* out = (float*)d_out;
    (void)in_sizes; (void)n_in; (void)out_size;

    cudaFuncSetAttribute(mma_gemm<false, false, false>, cudaFuncAttributeMaxDynamicSharedMemorySize, GEMM_SMEM);
    cudaFuncSetAttribute(mma_gemm<true, true, true>,    cudaFuncAttributeMaxDynamicSharedMemorySize, GEMM_SMEM);
    cudaFuncSetAttribute(mma_gemm<true, true, false>,   cudaFuncAttributeMaxDynamicSharedMemorySize, GEMM_SMEM);

    #define SYMADDR(p, s) float* p; cudaGetSymbolAddress((void**)&p, s)
    SYMADDR(p_xt, g_xt); SYMADDR(p_h4, g_h4);
    #define HADDR(p, s) __half* p; cudaGetSymbolAddress((void**)&p, s)
    HADDR(axh, g_axh); HADDR(axl, g_axl);
    HADDR(aah, g_aah); HADDR(aal, g_aal);
    HADDR(a2h, g_a2h); HADDR(a2l, g_a2l);
    HADDR(a3h, g_a3h); HADDR(a3l, g_a3l);
    HADDR(bgat, g_bgat); HADDR(bgcn, g_bgcn);
    HADDR(bg1, g_bg1); HADDR(bg2, g_bg2);

    // CSR build
    zero_small_kernel<<<(N_NODES + 255) / 256, 256>>>();
    deg_kernel<<<(E_TOT + 255) / 256, 256>>>(ei);
    scan_kernel<<<1, 1024>>>();
    fill_kernel<<<(E_TOT + 255) / 256, 256>>>(ei);
    dinv_kernel<<<(N_NODES + 255) / 256, 256>>>();

    // weight + input splits
    cvtB_kernel<<<(NP_GAT * KP_X + 255) / 256, 256>>>(W_gat, bgat, F_IN, D1, KP_X, NP_GAT * KP_X);
    cvtB_kernel<<<(NP_GCN * KP_AGG + 255) / 256, 256>>>(W_gcn, bgcn, D1, D2, KP_AGG, NP_GCN * KP_AGG);
    cvtB_kernel<<<(NP_G1 * KP_H2 + 255) / 256, 256>>>(W_g1, bg1, D2, D3, KP_H2, NP_G1 * KP_H2);
    cvtB_kernel<<<(NP_G2 * KP_H3 + 255) / 256, 256>>>(W_g2, bg2, D3, D4, KP_H3, NP_G2 * KP_H3);
    cvtA_kernel<<<(M_PAD * KP_X + 255) / 256, 256>>>(x, axh, axl, F_IN, KP_X, M_PAD * KP_X);

    // GAT linear: xt = x @ W_gat
    mma_gemm<false, false, false><<<dim3(NP_GAT / 128, M_PAD / 128), 256, GEMM_SMEM>>>(
        axh, axl, bgat, nullptr, p_xt, nullptr, nullptr, KP_X, KP_X / 32, D1, D1);

    attn_kernel<<<(N_NODES * HEADS + 255) / 256, 256>>>(att_s, att_d);
    w_kernel<<<(E_TOT + 255) / 256, 256>>>(ei);
    gat_gather_kernel<<<(N_NODES * 32 + 255) / 256, 256>>>(b_gat);
    gcn_gather_kernel<<<(N_NODES * 32 + 255) / 256, 256>>>();

    // GCN linear -> split fp16 directly
    mma_gemm<true, true, true><<<dim3(NP_GCN / 128, M_PAD / 128), 256, GEMM_SMEM>>>(
        aah, aal, bgcn, b_gcn, nullptr, a2h, a2l, KP_AGG, KP_AGG / 32, D2, KP_H2);
    // g1 -> split fp16 directly
    mma_gemm<true, true, true><<<dim3(NP_G1 / 128, M_PAD / 128), 256, GEMM_SMEM>>>(
        a2h, a2l, bg1, b_g1, nullptr, a3h, a3l, KP_H2, KP_H2 / 32, D3, KP_H3);
    // g2 -> fp32 h4
    mma_gemm<true, true, false><<<dim3(NP_G2 / 128, M_PAD / 128), 256, GEMM_SMEM>>>(
        a3h, a3l, bg2, b_g2, p_h4, nullptr, nullptr, KP_H3, KP_H3 / 32, D4, D4);

    tail_kernel<<<(N_NODES * 32 + 255) / 256, 256>>>(
        W_fc1, b_fc1, W_fc2, b_fc2, W_out, b_out, out);
}

// round 6
// speedup vs baseline: 3.6280x; 1.3486x over previous
#include <cuda_runtime.h>
#include <cuda_fp16.h>
#include <math.h>
#include <stdint.h>

#define N_NODES 10000
#define N_EDGES 120000
#define E_TOT   130000
#define F_IN    66
#define HEADS   10
#define FHEAD   66
#define D1      660
#define D2      1320
#define D3      1000
#define D4      64
#define M_PAD   10112        // 79 * 128

#define KP_X    96
#define KP_AGG  704
#define KP_H2   1344
#define KP_H3   1024
#define NP_GAT  768
#define NP_GCN  1408
#define NP_G1   1024
#define NP_G2   128

// ---------------- fp32 scratch ----------------------------------------------
__device__ __align__(16) float g_xt [N_NODES * D1];
__device__             float g_as [N_NODES * HEADS];
__device__             float g_ad [N_NODES * HEADS];
__device__             float g_dinv[N_NODES];
__device__ __align__(16) float g_h1 [N_NODES * D1];
__device__ __align__(16) float g_h4 [N_NODES * D4];

// ---------------- CSR over destination --------------------------------------
__device__ int g_deg_i [N_NODES];
__device__ int g_fill  [N_NODES];
__device__ int g_rowptr[N_NODES + 1];
__device__ int g_csr_src[E_TOT];

// ---------------- fp16 buffers ------------------------------------------------
__device__ __align__(16) __half g_axh [M_PAD * KP_X];
__device__ __align__(16) __half g_aah [M_PAD * KP_AGG];
__device__ __align__(16) __half g_a2h [M_PAD * KP_H2];
__device__ __align__(16) __half g_a3h [M_PAD * KP_H3];
__device__ __align__(16) __half g_bgat[NP_GAT * KP_X];
__device__ __align__(16) __half g_bgcn[NP_GCN * KP_AGG];
__device__ __align__(16) __half g_bg1 [NP_G1 * KP_H2];
__device__ __align__(16) __half g_bg2 [NP_G2 * KP_H3];

// ---------------- baseline-PTX helpers ---------------------------------------
__device__ __forceinline__ uint32_t smem_u32(const void* p) {
    uint32_t a;
    asm("{ .reg .u64 t; cvta.to.shared.u64 t, %1; cvt.u32.u64 %0, t; }" : "=r"(a) : "l"(p));
    return a;
}
__device__ __forceinline__ void cp16(uint32_t dst, const void* src) {
    asm volatile("cp.async.cg.shared.global [%0], [%1], 16;" :: "r"(dst), "l"(src));
}
__device__ __forceinline__ void cp_commit() { asm volatile("cp.async.commit_group;"); }
template<int N> __device__ __forceinline__ void cp_wait() {
    asm volatile("cp.async.wait_group %0;" :: "n"(N));
}
__device__ __forceinline__ void ldsm4(uint32_t* r, uint32_t addr) {
    asm volatile("ldmatrix.sync.aligned.m8n8.x4.shared.b16 {%0,%1,%2,%3}, [%4];"
        : "=r"(r[0]), "=r"(r[1]), "=r"(r[2]), "=r"(r[3]) : "r"(addr));
}
__device__ __forceinline__ void mma_f16(float* d, const uint32_t* a, const uint32_t* b) {
    asm volatile("mma.sync.aligned.m16n8k16.row.col.f32.f16.f16.f32 "
        "{%0,%1,%2,%3}, {%4,%5,%6,%7}, {%8,%9}, {%0,%1,%2,%3};"
        : "+f"(d[0]), "+f"(d[1]), "+f"(d[2]), "+f"(d[3])
        : "r"(a[0]), "r"(a[1]), "r"(a[2]), "r"(a[3]), "r"(b[0]), "r"(b[1]));
}

// ---------------- misc ---------------------------------------------------------
__device__ __forceinline__ void edge_sd(const int* ei, int e, int& s, int& d) {
    if (e < N_EDGES) { s = ei[e]; d = ei[N_EDGES + e]; }
    else             { s = d = e - N_EDGES; }
}
__device__ __forceinline__ float leaky(float v, float sl) { return v >= 0.f ? v : sl * v; }

// ---------------- CSR build ----------------------------------------------------
__global__ void zero_small_kernel() {
    int i = blockIdx.x * blockDim.x + threadIdx.x;
    if (i < N_NODES) { g_deg_i[i] = 0; g_fill[i] = 0; }
}
__global__ void deg_kernel(const int* __restrict__ ei) {
    int e = blockIdx.x * blockDim.x + threadIdx.x;
    if (e >= E_TOT) return;
    int s, d; edge_sd(ei, e, s, d);
    atomicAdd(&g_deg_i[d], 1);
}
__global__ void scan_kernel() {   // single block, 1024 threads
    __shared__ int sm[1024];
    int tid = threadIdx.x;
    int base = tid * 10;
    int local[10]; int sum = 0;
    #pragma unroll
    for (int i = 0; i < 10; i++) {
        int v = (base + i < N_NODES) ? g_deg_i[base + i] : 0;
        local[i] = sum; sum += v;
    }
    sm[tid] = sum; __syncthreads();
    for (int off = 1; off < 1024; off <<= 1) {
        int v = (tid >= off) ? sm[tid - off] : 0;
        __syncthreads();
        sm[tid] += v;
        __syncthreads();
    }
    int pre = (tid > 0) ? sm[tid - 1] : 0;
    #pragma unroll
    for (int i = 0; i < 10; i++)
        if (base + i < N_NODES) g_rowptr[base + i] = pre + local[i];
    if (tid == 1023) g_rowptr[N_NODES] = sm[1023];
}
__global__ void fill_kernel(const int* __restrict__ ei) {
    int e = blockIdx.x * blockDim.x + threadIdx.x;
    if (e >= E_TOT) return;
    int s, d; edge_sd(ei, e, s, d);
    int pos = atomicAdd(&g_fill[d], 1);
    g_csr_src[g_rowptr[d] + pos] = s;
}
__global__ void dinv_kernel() {
    int i = blockIdx.x * blockDim.x + threadIdx.x;
    if (i < N_NODES) g_dinv[i] = rsqrtf(fmaxf((float)g_deg_i[i], 1.f));
}

// ---------------- fp16 converts ----------------------------------------------
__global__ void cvtA_kernel(const float* __restrict__ in, __half* __restrict__ hi,
                            int K, int Kp, int total) {
    int idx = blockIdx.x * blockDim.x + threadIdx.x;
    if (idx >= total) return;
    int r = idx / Kp, c = idx - r * Kp;
    float v = (r < N_NODES && c < K) ? in[(long)r * K + c] : 0.f;
    hi[idx] = __float2half_rn(v);
}
__global__ void cvtB_kernel(const float* __restrict__ W, __half* __restrict__ hi,
                            int K, int Nn, int Kp, int total) {
    int idx = blockIdx.x * blockDim.x + threadIdx.x;
    if (idx >= total) return;
    int n = idx / Kp, k = idx - n * Kp;
    float v = (k < K && n < Nn) ? W[(long)k * Nn + n] : 0.f;
    hi[idx] = __float2half_rn(v);
}

// ---------------- HMMA GEMM (single fp16, 4-stage cp.async) -------------------
#define TSTRIDE  80
#define B_HI_OFF 10240
#define STAGE_SZ 20480
#define GEMM_SMEM (4 * STAGE_SZ)

__device__ __forceinline__ void fill_stage(uint32_t st,
        const __half* __restrict__ A, const __half* __restrict__ B,
        int m0, int n0, int Kp, int k0, int tid) {
    #pragma unroll
    for (int i = 0; i < 2; i++) {
        int lin = tid + i * 256;
        int r = lin >> 2, cc = lin & 3;
        uint32_t d = st + r * TSTRIDE + cc * 16;
        cp16(d,            (const char*)(A + (long)(m0 + r) * Kp + k0) + cc * 16);
        cp16(d + B_HI_OFF, (const char*)(B + (long)(n0 + r) * Kp + k0) + cc * 16);
    }
    cp_commit();
}

template<bool BIAS, bool ACT, bool SPLIT>
__global__ __launch_bounds__(256, 1)
void mma_gemm(const __half* __restrict__ Ah, const __half* __restrict__ Bh,
              const float* __restrict__ bias, float* __restrict__ C,
              __half* __restrict__ Sh,
              int Kp, int chunks, int Nreal, int ldC) {
    extern __shared__ char smem[];
    const uint32_t tile0 = smem_u32(smem);
    const int tid = threadIdx.x, wid = tid >> 5, lane = tid & 31;
    const int m0 = blockIdx.y * 128, n0 = blockIdx.x * 128;
    const int mwoff = (wid >> 1) * 32, nwoff = (wid & 1) * 64;

    const int mat = lane >> 3, mrow = lane & 7;
    uint32_t a_off[2], b_off[4];
    #pragma unroll
    for (int ti = 0; ti < 2; ti++)
        a_off[ti] = (uint32_t)((mwoff + ti * 16 + ((mat & 1) << 3) + mrow) * TSTRIDE
                               + (mat >> 1) * 16);
    #pragma unroll
    for (int nt = 0; nt < 4; nt++)
        b_off[nt] = (uint32_t)((nwoff + nt * 16 + ((mat >> 1) << 3) + mrow) * TSTRIDE
                               + (mat & 1) * 16);

    float acc[2][8][4] = {};

    fill_stage(tile0, Ah, Bh, m0, n0, Kp, 0, tid);
    if (chunks > 1) fill_stage(tile0 + STAGE_SZ, Ah, Bh, m0, n0, Kp, 32, tid);
    if (chunks > 2) fill_stage(tile0 + 2 * STAGE_SZ, Ah, Bh, m0, n0, Kp, 64, tid);

    for (int c = 0; c < chunks; c++) {
        if (c + 2 < chunks)      cp_wait<2>();
        else if (c + 1 < chunks) cp_wait<1>();
        else                     cp_wait<0>();
        __syncthreads();
        if (c + 3 < chunks)
            fill_stage(tile0 + ((c + 3) & 3) * STAGE_SZ, Ah, Bh,
                       m0, n0, Kp, (c + 3) * 32, tid);
        uint32_t sb = tile0 + (c & 3) * STAGE_SZ;
        #pragma unroll
        for (int kh = 0; kh < 2; kh++) {
            uint32_t ah[2][4], bh[4][4];
            #pragma unroll
            for (int ti = 0; ti < 2; ti++)
                ldsm4(ah[ti], sb + a_off[ti] + kh * 32);
            #pragma unroll
            for (int nt = 0; nt < 4; nt++)
                ldsm4(bh[nt], sb + B_HI_OFF + b_off[nt] + kh * 32);
            #pragma unroll
            for (int ti = 0; ti < 2; ti++)
                #pragma unroll
                for (int nt = 0; nt < 8; nt++)
                    mma_f16(acc[ti][nt], ah[ti], &bh[nt >> 1][(nt & 1) * 2]);
        }
    }

    const int lr = lane >> 2, lc = (lane & 3) * 2;
    #pragma unroll
    for (int ti = 0; ti < 2; ti++)
        #pragma unroll
        for (int rp = 0; rp < 2; rp++) {
            int gr = m0 + mwoff + ti * 16 + rp * 8 + lr;
            if (gr >= N_NODES) continue;
            if (!SPLIT) {
                float* crow = C + (long)gr * ldC;
                #pragma unroll
                for (int nt = 0; nt < 8; nt++) {
                    int gc = n0 + nwoff + nt * 8 + lc;
                    float v0 = acc[ti][nt][rp * 2 + 0];
                    float v1 = acc[ti][nt][rp * 2 + 1];
                    if (gc < Nreal) {
                        if (BIAS) v0 += bias[gc];
                        if (ACT)  v0 = leaky(v0, 0.01f);
                        crow[gc] = v0;
                    }
                    if (gc + 1 < Nreal) {
                        if (BIAS) v1 += bias[gc + 1];
                        if (ACT)  v1 = leaky(v1, 0.01f);
                        crow[gc + 1] = v1;
                    }
                }
            } else {
                __half* hr = Sh + (long)gr * ldC;
                #pragma unroll
                for (int nt = 0; nt < 8; nt++) {
                    int gc = n0 + nwoff + nt * 8 + lc;
                    if (gc >= ldC) continue;
                    float v0 = 0.f, v1 = 0.f;
                    if (gc < Nreal) {
                        v0 = acc[ti][nt][rp * 2 + 0];
                        if (BIAS) v0 += bias[gc];
                        if (ACT)  v0 = leaky(v0, 0.01f);
                    }
                    if (gc + 1 < Nreal) {
                        v1 = acc[ti][nt][rp * 2 + 1];
                        if (BIAS) v1 += bias[gc + 1];
                        if (ACT)  v1 = leaky(v1, 0.01f);
                    }
                    __half2 hp;
                    hp.x = __float2half_rn(v0);
                    hp.y = __float2half_rn(v1);
                    *(__half2*)(hr + gc) = hp;
                }
            }
        }
}

// ---------------- attention coefficients ------------------------------------
__global__ void attn_kernel(const float* __restrict__ att_src,
                            const float* __restrict__ att_dst) {
    int idx = blockIdx.x * blockDim.x + threadIdx.x;
    if (idx >= N_NODES * HEADS) return;
    int n = idx / HEADS, h = idx % HEADS;
    const float* xr = g_xt + n * D1 + h * FHEAD;
    const float* as = att_src + h * FHEAD;
    const float* ad = att_dst + h * FHEAD;
    float s = 0.f, d = 0.f;
    #pragma unroll
    for (int f = 0; f < FHEAD; f++) { float v = xr[f]; s += v * as[f]; d += v * ad[f]; }
    g_as[idx] = s; g_ad[idx] = d;
}

// ---------------- GAT gather: warp per destination node ----------------------
// softmax weights computed inline (shift-invariant; |e| bounded so exp is safe)
__global__ void gat_gather_kernel(const float* __restrict__ b_gat) {
    int gw = (blockIdx.x * blockDim.x + threadIdx.x) >> 5;
    int lane = threadIdx.x & 31;
    int wl = threadIdx.x >> 5;
    __shared__ float sal[8][HEADS];
    if (gw >= N_NODES) return;
    int beg = g_rowptr[gw], end = g_rowptr[gw + 1];

    float adl = (lane < HEADS) ? g_ad[gw * HEADS + lane] : 0.f;
    float ssum = 0.f;
    if (lane < HEADS)
        for (int i = beg; i < end; i++) {
            int src = g_csr_src[i];
            ssum += expf(leaky(g_as[src * HEADS + lane] + adl, 0.2f));
        }
    float inv = (lane < HEADS) ? 1.f / fmaxf(ssum, 1e-16f) : 0.f;

    float4 acc[6];
    #pragma unroll
    for (int j = 0; j < 6; j++) acc[j] = make_float4(0.f, 0.f, 0.f, 0.f);

    for (int i = beg; i < end; i++) {
        int src = g_csr_src[i];
        if (lane < HEADS)
            sal[wl][lane] = expf(leaky(g_as[src * HEADS + lane] + adl, 0.2f)) * inv;
        __syncwarp();
        const float4* xs = (const float4*)g_xt + src * (D1 / 4);
        #pragma unroll
        for (int j = 0; j < 6; j++) {
            int f4 = lane + 32 * j;
            if (f4 < D1 / 4) {
                float4 v = xs[f4];
                int f = 4 * f4;
                acc[j].x += v.x * sal[wl][ f      / FHEAD];
                acc[j].y += v.y * sal[wl][(f + 1) / FHEAD];
                acc[j].z += v.z * sal[wl][(f + 2) / FHEAD];
                acc[j].w += v.w * sal[wl][(f + 3) / FHEAD];
            }
        }
        __syncwarp();
    }

    const float4* b4 = (const float4*)b_gat;
    float4* hd = (float4*)g_h1 + gw * (D1 / 4);
    #pragma unroll
    for (int j = 0; j < 6; j++) {
        int f4 = lane + 32 * j;
        if (f4 < D1 / 4) {
            float4 b = b4[f4], r;
            r.x = leaky(acc[j].x + b.x, 0.01f);
            r.y = leaky(acc[j].y + b.y, 0.01f);
            r.z = leaky(acc[j].z + b.z, 0.01f);
            r.w = leaky(acc[j].w + b.w, 0.01f);
            hd[f4] = r;
        }
    }
}

// ---------------- GCN gather: warp per node, writes fp16 directly ------------
__global__ void gcn_gather_kernel() {
    int gw = (blockIdx.x * blockDim.x + threadIdx.x) >> 5;
    int lane = threadIdx.x & 31;
    if (gw >= N_NODES) return;
    int beg = g_rowptr[gw], end = g_rowptr[gw + 1];
    float dd = g_dinv[gw];

    float4 acc[6];
    #pragma unroll
    for (int j = 0; j < 6; j++) acc[j] = make_float4(0.f, 0.f, 0.f, 0.f);

    for (int i = beg; i < end; i++) {
        int src = g_csr_src[i];
        float nm = dd * g_dinv[src];
        const float4* hs = (const float4*)g_h1 + src * (D1 / 4);
        #pragma unroll
        for (int j = 0; j < 6; j++) {
            int f4 = lane + 32 * j;
            if (f4 < D1 / 4) {
                float4 v = hs[f4];
                acc[j].x += v.x * nm;
                acc[j].y += v.y * nm;
                acc[j].z += v.z * nm;
                acc[j].w += v.w * nm;
            }
        }
    }

    __half* hr = g_aah + (long)gw * KP_AGG;
    #pragma unroll
    for (int j = 0; j < 6; j++) {
        int f4 = lane + 32 * j;
        if (f4 < D1 / 4) {
            __half2 hp0, hp1;
            hp0.x = __float2half_rn(acc[j].x);
            hp0.y = __float2half_rn(acc[j].y);
            hp1.x = __float2half_rn(acc[j].z);
            hp1.y = __float2half_rn(acc[j].w);
            int c = 4 * f4;
            ((__half2*)(hr + c))[0] = hp0;
            ((__half2*)(hr + c))[1] = hp1;
        }
    }
    for (int c = D1 + lane; c < KP_AGG; c += 32)
        hr[c] = __float2half_rn(0.f);
}

// ---------------- tail ----------------------------------------------------------
__global__ void tail_kernel(const float* __restrict__ W1, const float* __restrict__ b1,
                            const float* __restrict__ W2, const float* __restrict__ b2,
                            const float* __restrict__ W3, const float* __restrict__ b3,
                            float* __restrict__ out) {
    int gw = (blockIdx.x * blockDim.x + threadIdx.x) >> 5;
    int lane = threadIdx.x & 31;
    if (gw >= N_NODES) return;
    float v0 = g_h4[gw * 64 + lane];
    float v1 = g_h4[gw * 64 + 32 + lane];
    float s = b1[lane];
    #pragma unroll
    for (int k = 0; k < 32; k++) s += __shfl_sync(0xffffffffu, v0, k) * W1[k * 32 + lane];
    #pragma unroll
    for (int k = 0; k < 32; k++) s += __shfl_sync(0xffffffffu, v1, k) * W1[(k + 32) * 32 + lane];
    float u = leaky(s, 0.01f);
    int j = lane & 15;
    float s2 = b2[j];
    #pragma unroll
    for (int k = 0; k < 32; k++) s2 += __shfl_sync(0xffffffffu, u, k) * W2[k * 16 + j];
    float t = leaky(s2, 0.01f);
    float o = (lane < 16) ? t * W3[lane] : 0.f;
    #pragma unroll
    for (int off = 8; off > 0; off >>= 1) o += __shfl_down_sync(0xffffffffu, o, off);
    if (lane == 0) out[gw] = o + b3[0];
}

// ---------------- launch ----------------------------------------------------------
extern "C" void kernel_launch(void* const* d_in, const int* in_sizes, int n_in,
                              void* d_out, int out_size) {
    const float* x     = (const float*)d_in[0];
    const int*   ei    = (const int*)  d_in[1];
    const float* W_gat = (const float*)d_in[2];
    const float* att_s = (const float*)d_in[3];
    const float* att_d = (const float*)d_in[4];
    const float* b_gat = (const float*)d_in[5];
    const float* W_gcn = (const float*)d_in[6];
    const float* b_gcn = (const float*)d_in[7];
    const float* W_g1  = (const float*)d_in[8];
    const float* b_g1  = (const float*)d_in[9];
    const float* W_g2  = (const float*)d_in[10];
    const float* b_g2  = (const float*)d_in[11];
    const float* W_fc1 = (const float*)d_in[12];
    const float* b_fc1 = (const float*)d_in[13];
    const float* W_fc2 = (const float*)d_in[14];
    const float* b_fc2 = (const float*)d_in[15];
    const float* W_out = (const float*)d_in[16];
    const float* b_out = (const float*)d_in[17];
    float* out = (float*)d_out;
    (void)in_sizes; (void)n_in; (void)out_size;

    cudaFuncSetAttribute(mma_gemm<false, false, false>, cudaFuncAttributeMaxDynamicSharedMemorySize, GEMM_SMEM);
    cudaFuncSetAttribute(mma_gemm<true, true, true>,    cudaFuncAttributeMaxDynamicSharedMemorySize, GEMM_SMEM);
    cudaFuncSetAttribute(mma_gemm<true, true, false>,   cudaFuncAttributeMaxDynamicSharedMemorySize, GEMM_SMEM);

    #define SYMADDR(p, s) float* p; cudaGetSymbolAddress((void**)&p, s)
    SYMADDR(p_xt, g_xt); SYMADDR(p_h4, g_h4);
    #define HADDR(p, s) __half* p; cudaGetSymbolAddress((void**)&p, s)
    HADDR(axh, g_axh); HADDR(aah, g_aah);
    HADDR(a2h, g_a2h); HADDR(a3h, g_a3h);
    HADDR(bgat, g_bgat); HADDR(bgcn, g_bgcn);
    HADDR(bg1, g_bg1); HADDR(bg2, g_bg2);

    // CSR build
    zero_small_kernel<<<(N_NODES + 255) / 256, 256>>>();
    deg_kernel<<<(E_TOT + 255) / 256, 256>>>(ei);
    scan_kernel<<<1, 1024>>>();
    fill_kernel<<<(E_TOT + 255) / 256, 256>>>(ei);
    dinv_kernel<<<(N_NODES + 255) / 256, 256>>>();

    // converts
    cvtB_kernel<<<(NP_GAT * KP_X + 255) / 256, 256>>>(W_gat, bgat, F_IN, D1, KP_X, NP_GAT * KP_X);
    cvtB_kernel<<<(NP_GCN * KP_AGG + 255) / 256, 256>>>(W_gcn, bgcn, D1, D2, KP_AGG, NP_GCN * KP_AGG);
    cvtB_kernel<<<(NP_G1 * KP_H2 + 255) / 256, 256>>>(W_g1, bg1, D2, D3, KP_H2, NP_G1 * KP_H2);
    cvtB_kernel<<<(NP_G2 * KP_H3 + 255) / 256, 256>>>(W_g2, bg2, D3, D4, KP_H3, NP_G2 * KP_H3);
    cvtA_kernel<<<(M_PAD * KP_X + 255) / 256, 256>>>(x, axh, F_IN, KP_X, M_PAD * KP_X);

    // GAT linear: xt = x @ W_gat
    mma_gemm<false, false, false><<<dim3(NP_GAT / 128, M_PAD / 128), 256, GEMM_SMEM>>>(
        axh, bgat, nullptr, p_xt, nullptr, KP_X, KP_X / 32, D1, D1);

    attn_kernel<<<(N_NODES * HEADS + 255) / 256, 256>>>(att_s, att_d);
    gat_gather_kernel<<<(N_NODES * 32 + 255) / 256, 256>>>(b_gat);
    gcn_gather_kernel<<<(N_NODES * 32 + 255) / 256, 256>>>();

    // GCN linear -> fp16 directly
    mma_gemm<true, true, true><<<dim3(NP_GCN / 128, M_PAD / 128), 256, GEMM_SMEM>>>(
        aah, bgcn, b_gcn, nullptr, a2h, KP_AGG, KP_AGG / 32, D2, KP_H2);
    // g1 -> fp16 directly
    mma_gemm<true, true, true><<<dim3(NP_G1 / 128, M_PAD / 128), 256, GEMM_SMEM>>>(
        a2h, bg1, b_g1, nullptr, a3h, KP_H2, KP_H2 / 32, D3, KP_H3);
    // g2 -> fp32 h4
    mma_gemm<true, true, false><<<dim3(NP_G2 / 128, M_PAD / 128), 256, GEMM_SMEM>>>(
        a3h, bg2, b_g2, p_h4, nullptr, KP_H3, KP_H3 / 32, D4, D4);

    tail_kernel<<<(N_NODES * 32 + 255) / 256, 256>>>(
        W_fc1, b_fc1, W_fc2, b_fc2, W_out, b_out, out);
}

// round 7
// speedup vs baseline: 3.7424x; 1.0315x over previous
#include <cuda_runtime.h>
#include <cuda_fp16.h>
#include <math.h>
#include <stdint.h>

#define N_NODES 10000
#define N_EDGES 120000
#define E_TOT   130000
#define F_IN    66
#define HEADS   10
#define FHEAD   66
#define D1      660
#define D2      1320
#define D3      1000
#define D4      64
#define M_PAD   10112        // 79 * 128

#define KP_X    96
#define KP_AGG  704
#define KP_H2   1344
#define KP_H3   1024
#define NP_GAT  768
#define NP_GCN  1408
#define NP_G1   1024
#define NP_G2   128
#define XTS     672          // fp16 row stride for xt / h1 (84 float4)

// ---------------- scratch ------------------------------------------------------
__device__             float g_as [N_NODES * HEADS];
__device__             float g_ad [N_NODES * HEADS];
__device__             float g_dinv[N_NODES];
__device__ __align__(16) float g_h4 [N_NODES * D4];

// fp16 feature tensors (row stride XTS, cols >= D1 zeroed)
__device__ __align__(16) __half g_xth [N_NODES * XTS];
__device__ __align__(16) __half g_h1h [N_NODES * XTS];

// ---------------- CSR over destination ------------------------------------------
__device__ int g_deg_i [N_NODES];
__device__ int g_fill  [N_NODES];
__device__ int g_rowptr[N_NODES + 1];
__device__ int g_csr_src[E_TOT];

// ---------------- fp16 GEMM buffers ----------------------------------------------
__device__ __align__(16) __half g_axh [M_PAD * KP_X];
__device__ __align__(16) __half g_aah [M_PAD * KP_AGG];
__device__ __align__(16) __half g_a2h [M_PAD * KP_H2];
__device__ __align__(16) __half g_a3h [M_PAD * KP_H3];
__device__ __align__(16) __half g_bgat[NP_GAT * KP_X];
__device__ __align__(16) __half g_bgcn[NP_GCN * KP_AGG];
__device__ __align__(16) __half g_bg1 [NP_G1 * KP_H2];
__device__ __align__(16) __half g_bg2 [NP_G2 * KP_H3];

// ---------------- baseline-PTX helpers -------------------------------------------
__device__ __forceinline__ uint32_t smem_u32(const void* p) {
    uint32_t a;
    asm("{ .reg .u64 t; cvta.to.shared.u64 t, %1; cvt.u32.u64 %0, t; }" : "=r"(a) : "l"(p));
    return a;
}
__device__ __forceinline__ void cp16(uint32_t dst, const void* src) {
    asm volatile("cp.async.cg.shared.global [%0], [%1], 16;" :: "r"(dst), "l"(src));
}
__device__ __forceinline__ void cp_commit() { asm volatile("cp.async.commit_group;"); }
template<int N> __device__ __forceinline__ void cp_wait() {
    asm volatile("cp.async.wait_group %0;" :: "n"(N));
}
__device__ __forceinline__ void ldsm4(uint32_t* r, uint32_t addr) {
    asm volatile("ldmatrix.sync.aligned.m8n8.x4.shared.b16 {%0,%1,%2,%3}, [%4];"
        : "=r"(r[0]), "=r"(r[1]), "=r"(r[2]), "=r"(r[3]) : "r"(addr));
}
__device__ __forceinline__ void mma_f16(float* d, const uint32_t* a, const uint32_t* b) {
    asm volatile("mma.sync.aligned.m16n8k16.row.col.f32.f16.f16.f32 "
        "{%0,%1,%2,%3}, {%4,%5,%6,%7}, {%8,%9}, {%0,%1,%2,%3};"
        : "+f"(d[0]), "+f"(d[1]), "+f"(d[2]), "+f"(d[3])
        : "r"(a[0]), "r"(a[1]), "r"(a[2]), "r"(a[3]), "r"(b[0]), "r"(b[1]));
}

// ---------------- misc ------------------------------------------------------------
__device__ __forceinline__ void edge_sd(const int* ei, int e, int& s, int& d) {
    if (e < N_EDGES) { s = ei[e]; d = ei[N_EDGES + e]; }
    else             { s = d = e - N_EDGES; }
}
__device__ __forceinline__ float leaky(float v, float sl) { return v >= 0.f ? v : sl * v; }

// ---------------- CSR build ---------------------------------------------------------
__global__ void zero_small_kernel() {
    int i = blockIdx.x * blockDim.x + threadIdx.x;
    if (i < N_NODES) { g_deg_i[i] = 0; g_fill[i] = 0; }
}
__global__ void deg_kernel(const int* __restrict__ ei) {
    int e = blockIdx.x * blockDim.x + threadIdx.x;
    if (e >= E_TOT) return;
    int s, d; edge_sd(ei, e, s, d);
    atomicAdd(&g_deg_i[d], 1);
}
__global__ void scan_kernel() {   // single block; also computes dinv
    __shared__ int sm[1024];
    int tid = threadIdx.x;
    int base = tid * 10;
    int local[10]; int sum = 0;
    #pragma unroll
    for (int i = 0; i < 10; i++) {
        int v = (base + i < N_NODES) ? g_deg_i[base + i] : 0;
        if (base + i < N_NODES) g_dinv[base + i] = rsqrtf(fmaxf((float)v, 1.f));
        local[i] = sum; sum += v;
    }
    sm[tid] = sum; __syncthreads();
    for (int off = 1; off < 1024; off <<= 1) {
        int v = (tid >= off) ? sm[tid - off] : 0;
        __syncthreads();
        sm[tid] += v;
        __syncthreads();
    }
    int pre = (tid > 0) ? sm[tid - 1] : 0;
    #pragma unroll
    for (int i = 0; i < 10; i++)
        if (base + i < N_NODES) g_rowptr[base + i] = pre + local[i];
    if (tid == 1023) g_rowptr[N_NODES] = sm[1023];
}
__global__ void fill_kernel(const int* __restrict__ ei) {
    int e = blockIdx.x * blockDim.x + threadIdx.x;
    if (e >= E_TOT) return;
    int s, d; edge_sd(ei, e, s, d);
    int pos = atomicAdd(&g_fill[d], 1);
    g_csr_src[g_rowptr[d] + pos] = s;
}

// ---------------- fp16 converts -------------------------------------------------------
__global__ void cvtA_kernel(const float* __restrict__ in, __half* __restrict__ hi,
                            int K, int Kp, int total) {
    int idx = blockIdx.x * blockDim.x + threadIdx.x;
    if (idx >= total) return;
    int r = idx / Kp, c = idx - r * Kp;
    float v = (r < N_NODES && c < K) ? in[(long)r * K + c] : 0.f;
    hi[idx] = __float2half_rn(v);
}
__global__ void cvtB_kernel(const float* __restrict__ W, __half* __restrict__ hi,
                            int K, int Nn, int Kp, int total) {
    int idx = blockIdx.x * blockDim.x + threadIdx.x;
    if (idx >= total) return;
    int n = idx / Kp, k = idx - n * Kp;
    float v = (k < K && n < Nn) ? W[(long)k * Nn + n] : 0.f;
    hi[idx] = __float2half_rn(v);
}

// ---------------- HMMA GEMM (single fp16, 4-stage cp.async) ---------------------------
#define TSTRIDE  80
#define B_HI_OFF 10240
#define STAGE_SZ 20480
#define GEMM_SMEM (4 * STAGE_SZ)

__device__ __forceinline__ void fill_stage(uint32_t st,
        const __half* __restrict__ A, const __half* __restrict__ B,
        int m0, int n0, int Kp, int k0, int tid) {
    #pragma unroll
    for (int i = 0; i < 2; i++) {
        int lin = tid + i * 256;
        int r = lin >> 2, cc = lin & 3;
        uint32_t d = st + r * TSTRIDE + cc * 16;
        cp16(d,            (const char*)(A + (long)(m0 + r) * Kp + k0) + cc * 16);
        cp16(d + B_HI_OFF, (const char*)(B + (long)(n0 + r) * Kp + k0) + cc * 16);
    }
    cp_commit();
}

template<bool BIAS, bool ACT, bool SPLIT>
__global__ __launch_bounds__(256, 1)
void mma_gemm(const __half* __restrict__ Ah, const __half* __restrict__ Bh,
              const float* __restrict__ bias, float* __restrict__ C,
              __half* __restrict__ Sh,
              int Kp, int chunks, int Nreal, int ldC) {
    extern __shared__ char smem[];
    const uint32_t tile0 = smem_u32(smem);
    const int tid = threadIdx.x, wid = tid >> 5, lane = tid & 31;
    const int m0 = blockIdx.y * 128, n0 = blockIdx.x * 128;
    const int mwoff = (wid >> 1) * 32, nwoff = (wid & 1) * 64;

    const int mat = lane >> 3, mrow = lane & 7;
    uint32_t a_off[2], b_off[4];
    #pragma unroll
    for (int ti = 0; ti < 2; ti++)
        a_off[ti] = (uint32_t)((mwoff + ti * 16 + ((mat & 1) << 3) + mrow) * TSTRIDE
                               + (mat >> 1) * 16);
    #pragma unroll
    for (int nt = 0; nt < 4; nt++)
        b_off[nt] = (uint32_t)((nwoff + nt * 16 + ((mat >> 1) << 3) + mrow) * TSTRIDE
                               + (mat & 1) * 16);

    float acc[2][8][4] = {};

    fill_stage(tile0, Ah, Bh, m0, n0, Kp, 0, tid);
    if (chunks > 1) fill_stage(tile0 + STAGE_SZ, Ah, Bh, m0, n0, Kp, 32, tid);
    if (chunks > 2) fill_stage(tile0 + 2 * STAGE_SZ, Ah, Bh, m0, n0, Kp, 64, tid);

    for (int c = 0; c < chunks; c++) {
        if (c + 2 < chunks)      cp_wait<2>();
        else if (c + 1 < chunks) cp_wait<1>();
        else                     cp_wait<0>();
        __syncthreads();
        if (c + 3 < chunks)
            fill_stage(tile0 + ((c + 3) & 3) * STAGE_SZ, Ah, Bh,
                       m0, n0, Kp, (c + 3) * 32, tid);
        uint32_t sb = tile0 + (c & 3) * STAGE_SZ;
        #pragma unroll
        for (int kh = 0; kh < 2; kh++) {
            uint32_t ah[2][4], bh[4][4];
            #pragma unroll
            for (int ti = 0; ti < 2; ti++)
                ldsm4(ah[ti], sb + a_off[ti] + kh * 32);
            #pragma unroll
            for (int nt = 0; nt < 4; nt++)
                ldsm4(bh[nt], sb + B_HI_OFF + b_off[nt] + kh * 32);
            #pragma unroll
            for (int ti = 0; ti < 2; ti++)
                #pragma unroll
                for (int nt = 0; nt < 8; nt++)
                    mma_f16(acc[ti][nt], ah[ti], &bh[nt >> 1][(nt & 1) * 2]);
        }
    }

    const int lr = lane >> 2, lc = (lane & 3) * 2;
    #pragma unroll
    for (int ti = 0; ti < 2; ti++)
        #pragma unroll
        for (int rp = 0; rp < 2; rp++) {
            int gr = m0 + mwoff + ti * 16 + rp * 8 + lr;
            if (gr >= N_NODES) continue;
            if (!SPLIT) {
                float* crow = C + (long)gr * ldC;
                #pragma unroll
                for (int nt = 0; nt < 8; nt++) {
                    int gc = n0 + nwoff + nt * 8 + lc;
                    float v0 = acc[ti][nt][rp * 2 + 0];
                    float v1 = acc[ti][nt][rp * 2 + 1];
                    if (gc < Nreal) {
                        if (BIAS) v0 += bias[gc];
                        if (ACT)  v0 = leaky(v0, 0.01f);
                        crow[gc] = v0;
                    }
                    if (gc + 1 < Nreal) {
                        if (BIAS) v1 += bias[gc + 1];
                        if (ACT)  v1 = leaky(v1, 0.01f);
                        crow[gc + 1] = v1;
                    }
                }
            } else {
                __half* hr = Sh + (long)gr * ldC;
                #pragma unroll
                for (int nt = 0; nt < 8; nt++) {
                    int gc = n0 + nwoff + nt * 8 + lc;
                    if (gc >= ldC) continue;
                    float v0 = 0.f, v1 = 0.f;
                    if (gc < Nreal) {
                        v0 = acc[ti][nt][rp * 2 + 0];
                        if (BIAS) v0 += bias[gc];
                        if (ACT)  v0 = leaky(v0, 0.01f);
                    }
                    if (gc + 1 < Nreal) {
                        v1 = acc[ti][nt][rp * 2 + 1];
                        if (BIAS) v1 += bias[gc + 1];
                        if (ACT)  v1 = leaky(v1, 0.01f);
                    }
                    __half2 hp;
                    hp.x = __float2half_rn(v0);
                    hp.y = __float2half_rn(v1);
                    *(__half2*)(hr + gc) = hp;
                }
            }
        }
}

// ---------------- attention coefficients (fp16 xt) -----------------------------
__global__ void attn_kernel(const float* __restrict__ att_src,
                            const float* __restrict__ att_dst) {
    int idx = blockIdx.x * blockDim.x + threadIdx.x;
    if (idx >= N_NODES * HEADS) return;
    int n = idx / HEADS, h = idx % HEADS;
    const __half* xr = g_xth + (long)n * XTS + h * FHEAD;
    const float* as = att_src + h * FHEAD;
    const float* ad = att_dst + h * FHEAD;
    float s = 0.f, d = 0.f;
    #pragma unroll
    for (int f = 0; f < FHEAD; f++) {
        float v = __half2float(xr[f]);
        s += v * as[f]; d += v * ad[f];
    }
    g_as[idx] = s; g_ad[idx] = d;
}

// ---------------- GAT gather (fp16 features, warp per dst node) -----------------
__global__ void gat_gather_kernel(const float* __restrict__ b_gat) {
    int gw = (blockIdx.x * blockDim.x + threadIdx.x) >> 5;
    int lane = threadIdx.x & 31;
    int wl = threadIdx.x >> 5;
    __shared__ float sal[8][12];
    if (gw >= N_NODES) return;
    int beg = g_rowptr[gw], end = g_rowptr[gw + 1];

    float adl = (lane < HEADS) ? g_ad[gw * HEADS + lane] : 0.f;
    float ssum = 0.f;
    if (lane < HEADS)
        for (int i = beg; i < end; i++) {
            int src = g_csr_src[i];
            ssum += expf(leaky(g_as[src * HEADS + lane] + adl, 0.2f));
        }
    float inv = (lane < HEADS) ? 1.f / fmaxf(ssum, 1e-16f) : 0.f;

    // per-j head split: elements [f4*8, f4*8+8) span heads h0j / h0j+1 at posj
    int h0[3], pos[3], valid[3];
    #pragma unroll
    for (int j = 0; j < 3; j++) {
        int f4 = lane + 32 * j;
        valid[j] = (f4 < XTS / 8);
        int f0 = f4 * 8;
        int hh = f0 / FHEAD; if (hh > 9) hh = 9;
        h0[j] = hh;
        pos[j] = (hh + 1) * FHEAD - f0;   // k < pos -> head h0, else h0+1
    }

    float acc[3][8] = {};

    for (int i = beg; i < end; i++) {
        int src = g_csr_src[i];
        if (lane < 12)
            sal[wl][lane] = (lane < HEADS)
                ? expf(leaky(g_as[src * HEADS + lane] + adl, 0.2f)) * inv : 0.f;
        __syncwarp();
        const float4* xs = (const float4*)(g_xth + (long)src * XTS);
        #pragma unroll
        for (int j = 0; j < 3; j++) {
            if (!valid[j]) continue;
            float4 raw = xs[lane + 32 * j];
            const __half2* hp = (const __half2*)&raw;
            float s0 = sal[wl][h0[j]], s1 = sal[wl][h0[j] + 1];
            #pragma unroll
            for (int k = 0; k < 4; k++) {
                float2 v = __half22float2(hp[k]);
                acc[j][2 * k + 0] += v.x * (2 * k     < pos[j] ? s0 : s1);
                acc[j][2 * k + 1] += v.y * (2 * k + 1 < pos[j] ? s0 : s1);
            }
        }
        __syncwarp();
    }

    __half* hd = g_h1h + (long)gw * XTS;
    #pragma unroll
    for (int j = 0; j < 3; j++) {
        if (!valid[j]) continue;
        int f0 = (lane + 32 * j) * 8;
        __half2 o[4];
        #pragma unroll
        for (int k = 0; k < 8; k++) {
            int f = f0 + k;
            float v = (f < D1) ? leaky(acc[j][k] + b_gat[f], 0.01f) : 0.f;
            ((__half*)o)[k] = __float2half_rn(v);
        }
        *(float4*)(hd + f0) = *(float4*)o;
    }
}

// ---------------- GCN gather (fp16, warp per node) -> fp16 agg -------------------
__global__ void gcn_gather_kernel() {
    int gw = (blockIdx.x * blockDim.x + threadIdx.x) >> 5;
    int lane = threadIdx.x & 31;
    if (gw >= N_NODES) return;
    int beg = g_rowptr[gw], end = g_rowptr[gw + 1];
    float dd = g_dinv[gw];

    float acc[3][8] = {};
    int valid[3];
    #pragma unroll
    for (int j = 0; j < 3; j++) valid[j] = (lane + 32 * j) < XTS / 8;

    for (int i = beg; i < end; i++) {
        int src = g_csr_src[i];
        float nm = dd * g_dinv[src];
        const float4* hs = (const float4*)(g_h1h + (long)src * XTS);
        #pragma unroll
        for (int j = 0; j < 3; j++) {
            if (!valid[j]) continue;
            float4 raw = hs[lane + 32 * j];
            const __half2* hp = (const __half2*)&raw;
            #pragma unroll
            for (int k = 0; k < 4; k++) {
                float2 v = __half22float2(hp[k]);
                acc[j][2 * k + 0] += v.x * nm;
                acc[j][2 * k + 1] += v.y * nm;
            }
        }
    }

    __half* hr = g_aah + (long)gw * KP_AGG;
    #pragma unroll
    for (int j = 0; j < 3; j++) {
        if (!valid[j]) continue;
        int f0 = (lane + 32 * j) * 8;
        __half2 o[4];
        #pragma unroll
        for (int k = 0; k < 8; k++)
            ((__half*)o)[k] = __float2half_rn(acc[j][k]);
        *(float4*)(hr + f0) = *(float4*)o;
    }
    // zero pad cols [XTS, KP_AGG)
    for (int c = XTS + lane; c < KP_AGG; c += 32)
        hr[c] = __float2half_rn(0.f);
}

// ---------------- tail --------------------------------------------------------------
__global__ void tail_kernel(const float* __restrict__ W1, const float* __restrict__ b1,
                            const float* __restrict__ W2, const float* __restrict__ b2,
                            const float* __restrict__ W3, const float* __restrict__ b3,
                            float* __restrict__ out) {
    int gw = (blockIdx.x * blockDim.x + threadIdx.x) >> 5;
    int lane = threadIdx.x & 31;
    if (gw >= N_NODES) return;
    float v0 = g_h4[gw * 64 + lane];
    float v1 = g_h4[gw * 64 + 32 + lane];
    float s = b1[lane];
    #pragma unroll
    for (int k = 0; k < 32; k++) s += __shfl_sync(0xffffffffu, v0, k) * W1[k * 32 + lane];
    #pragma unroll
    for (int k = 0; k < 32; k++) s += __shfl_sync(0xffffffffu, v1, k) * W1[(k + 32) * 32 + lane];
    float u = leaky(s, 0.01f);
    int j = lane & 15;
    float s2 = b2[j];
    #pragma unroll
    for (int k = 0; k < 32; k++) s2 += __shfl_sync(0xffffffffu, u, k) * W2[k * 16 + j];
    float t = leaky(s2, 0.01f);
    float o = (lane < 16) ? t * W3[lane] : 0.f;
    #pragma unroll
    for (int off = 8; off > 0; off >>= 1) o += __shfl_down_sync(0xffffffffu, o, off);
    if (lane == 0) out[gw] = o + b3[0];
}

// ---------------- launch --------------------------------------------------------------
extern "C" void kernel_launch(void* const* d_in, const int* in_sizes, int n_in,
                              void* d_out, int out_size) {
    const float* x     = (const float*)d_in[0];
    const int*   ei    = (const int*)  d_in[1];
    const float* W_gat = (const float*)d_in[2];
    const float* att_s = (const float*)d_in[3];
    const float* att_d = (const float*)d_in[4];
    const float* b_gat = (const float*)d_in[5];
    const float* W_gcn = (const float*)d_in[6];
    const float* b_gcn = (const float*)d_in[7];
    const float* W_g1  = (const float*)d_in[8];
    const float* b_g1  = (const float*)d_in[9];
    const float* W_g2  = (const float*)d_in[10];
    const float* b_g2  = (const float*)d_in[11];
    const float* W_fc1 = (const float*)d_in[12];
    const float* b_fc1 = (const float*)d_in[13];
    const float* W_fc2 = (const float*)d_in[14];
    const float* b_fc2 = (const float*)d_in[15];
    const float* W_out = (const float*)d_in[16];
    const float* b_out = (const float*)d_in[17];
    float* out = (float*)d_out;
    (void)in_sizes; (void)n_in; (void)out_size;

    cudaFuncSetAttribute(mma_gemm<false, false, true>, cudaFuncAttributeMaxDynamicSharedMemorySize, GEMM_SMEM);
    cudaFuncSetAttribute(mma_gemm<true, true, true>,   cudaFuncAttributeMaxDynamicSharedMemorySize, GEMM_SMEM);
    cudaFuncSetAttribute(mma_gemm<true, true, false>,  cudaFuncAttributeMaxDynamicSharedMemorySize, GEMM_SMEM);

    float* p_h4; cudaGetSymbolAddress((void**)&p_h4, g_h4);
    #define HADDR(p, s) __half* p; cudaGetSymbolAddress((void**)&p, s)
    HADDR(axh, g_axh); HADDR(aah, g_aah);
    HADDR(a2h, g_a2h); HADDR(a3h, g_a3h);
    HADDR(bgat, g_bgat); HADDR(bgcn, g_bgcn);
    HADDR(bg1, g_bg1); HADDR(bg2, g_bg2);
    HADDR(xth, g_xth);

    // CSR build
    zero_small_kernel<<<(N_NODES + 255) / 256, 256>>>();
    deg_kernel<<<(E_TOT + 255) / 256, 256>>>(ei);
    scan_kernel<<<1, 1024>>>();
    fill_kernel<<<(E_TOT + 255) / 256, 256>>>(ei);

    // converts
    cvtB_kernel<<<(NP_GAT * KP_X + 255) / 256, 256>>>(W_gat, bgat, F_IN, D1, KP_X, NP_GAT * KP_X);
    cvtB_kernel<<<(NP_GCN * KP_AGG + 255) / 256, 256>>>(W_gcn, bgcn, D1, D2, KP_AGG, NP_GCN * KP_AGG);
    cvtB_kernel<<<(NP_G1 * KP_H2 + 255) / 256, 256>>>(W_g1, bg1, D2, D3, KP_H2, NP_G1 * KP_H2);
    cvtB_kernel<<<(NP_G2 * KP_H3 + 255) / 256, 256>>>(W_g2, bg2, D3, D4, KP_H3, NP_G2 * KP_H3);
    cvtA_kernel<<<(M_PAD * KP_X + 255) / 256, 256>>>(x, axh, F_IN, KP_X, M_PAD * KP_X);

    // GAT linear -> fp16 xt (row stride XTS)
    mma_gemm<false, false, true><<<dim3(NP_GAT / 128, M_PAD / 128), 256, GEMM_SMEM>>>(
        axh, bgat, nullptr, nullptr, xth, KP_X, KP_X / 32, D1, XTS);

    attn_kernel<<<(N_NODES * HEADS + 255) / 256, 256>>>(att_s, att_d);
    gat_gather_kernel<<<(N_NODES * 32 + 255) / 256, 256>>>(b_gat);
    gcn_gather_kernel<<<(N_NODES * 32 + 255) / 256, 256>>>();

    // GCN linear -> fp16
    mma_gemm<true, true, true><<<dim3(NP_GCN / 128, M_PAD / 128), 256, GEMM_SMEM>>>(
        aah, bgcn, b_gcn, nullptr, a2h, KP_AGG, KP_AGG / 32, D2, KP_H2);
    // g1 -> fp16
    mma_gemm<true, true, true><<<dim3(NP_G1 / 128, M_PAD / 128), 256, GEMM_SMEM>>>(
        a2h, bg1, b_g1, nullptr, a3h, KP_H2, KP_H2 / 32, D3, KP_H3);
    // g2 -> fp32 h4
    mma_gemm<true, true, false><<<dim3(NP_G2 / 128, M_PAD / 128), 256, GEMM_SMEM>>>(
        a3h, bg2, b_g2, p_h4, nullptr, KP_H3, KP_H3 / 32, D4, D4);

    tail_kernel<<<(N_NODES * 32 + 255) / 256, 256>>>(
        W_fc1, b_fc1, W_fc2, b_fc2, W_out, b_out, out);
}